// round 4
// baseline (speedup 1.0000x reference)
#include <cuda_runtime.h>
#include <math_constants.h>
#include <cstdint>

#define BATCH 2
#define SEQ 2048
#define DMODEL 1024
#define NHEADS 16
#define HDIM 64
#define ROWS (BATCH*SEQ)   // 4096

// Scratch (allocation-free rule: __device__ globals). 16 MB each.
__device__ float g_q[(size_t)ROWS * DMODEL];
__device__ float g_k[(size_t)ROWS * DMODEL];
__device__ float g_v[(size_t)ROWS * DMODEL];
__device__ float g_att[(size_t)ROWS * DMODEL];

// ===========================================================================
// Helpers
// ===========================================================================
__device__ __forceinline__ uint32_t smem_u32(const void* p) {
    uint32_t a;
    asm("{ .reg .u64 t; cvta.to.shared.u64 t, %1; cvt.u32.u64 %0, t; }"
        : "=r"(a) : "l"(p));
    return a;
}
__device__ __forceinline__ void cp_async16(uint32_t dst, const void* src) {
    asm volatile("cp.async.cg.shared.global [%0], [%1], 16;"
                 :: "r"(dst), "l"(src));
}
#define CP_COMMIT() asm volatile("cp.async.commit_group;" ::: "memory")
#define CP_WAIT(n)  asm volatile("cp.async.wait_group %0;" :: "n"(n) : "memory")

__device__ __forceinline__ uint32_t f2tf32(float f) {
    uint32_t r;
    asm("cvt.rna.tf32.f32 %0, %1;" : "=r"(r) : "f"(f));
    return r;
}
__device__ __forceinline__ void mma_tf32(float c[4],
                                         const uint32_t a[4],
                                         const uint32_t b[2]) {
    asm volatile(
        "mma.sync.aligned.m16n8k8.row.col.f32.tf32.tf32.f32 "
        "{%0,%1,%2,%3}, {%4,%5,%6,%7}, {%8,%9}, {%0,%1,%2,%3};"
        : "+f"(c[0]), "+f"(c[1]), "+f"(c[2]), "+f"(c[3])
        : "r"(a[0]), "r"(a[1]), "r"(a[2]), "r"(a[3]), "r"(b[0]), "r"(b[1]));
}

// ===========================================================================
// tf32 mma.sync SGEMM_NT: C[crow0:+128, ccol0:+128] = A[.,1024] * Bw[.,1024]^T
// 256 threads = 8 warps (4 along M x 2 along N), warp tile 32x64.
// BK=16, double-buffered cp.async. Smem row stride 20 words -> conflict-free
// fragment loads (banks 20*gid + tig all distinct within a warp).
// ===========================================================================
constexpr int TCK    = 16;                 // BK
constexpr int NCHUNK = DMODEL / TCK;       // 64
constexpr int SSTR   = 20;                 // smem row stride in floats

__device__ __forceinline__ void gemm_mma_tile(
    const float* __restrict__ A, const float* __restrict__ Bw,
    float* __restrict__ C, int crow0, int ccol0)
{
    __shared__ float As[2][128][SSTR];
    __shared__ float Bs[2][128][SSTR];

    const int tid  = threadIdx.x;
    const int wid  = tid >> 5;
    const int lane = tid & 31;
    const int wm   = wid & 3;          // warp row: 32-row band
    const int wn   = wid >> 2;         // warp col: 64-col band
    const int gid  = lane >> 2;        // 0..7
    const int tig  = lane & 3;         // 0..3

    const float* gA = A  + (size_t)crow0 * DMODEL;
    const float* gB = Bw + (size_t)ccol0 * DMODEL;

    auto load_chunk = [&](int c) {
        const int st = c & 1;
        #pragma unroll
        for (int i = 0; i < 2; i++) {
            const int idx = i * 256 + tid;       // [0,512) float4 slots
            const int row = idx >> 2, c4 = idx & 3;
            const size_t g = (size_t)row * DMODEL + c * TCK + c4 * 4;
            cp_async16(smem_u32(&As[st][row][c4 * 4]), gA + g);
            cp_async16(smem_u32(&Bs[st][row][c4 * 4]), gB + g);
        }
        CP_COMMIT();
    };

    float acc[2][8][4];
    #pragma unroll
    for (int mi = 0; mi < 2; mi++)
        #pragma unroll
        for (int ni = 0; ni < 8; ni++)
            #pragma unroll
            for (int r = 0; r < 4; r++) acc[mi][ni][r] = 0.f;

    load_chunk(0);

    for (int c = 0; c < NCHUNK; c++) {
        if (c + 1 < NCHUNK) {
            load_chunk(c + 1);
            CP_WAIT(1);
        } else {
            CP_WAIT(0);
        }
        __syncthreads();

        const int st = c & 1;
        #pragma unroll
        for (int ks = 0; ks < 2; ks++) {
            const int kb = ks * 8;
            uint32_t af[2][4];
            #pragma unroll
            for (int mi = 0; mi < 2; mi++) {
                const int r0 = wm * 32 + mi * 16 + gid;
                af[mi][0] = f2tf32(As[st][r0    ][kb + tig]);
                af[mi][1] = f2tf32(As[st][r0 + 8][kb + tig]);
                af[mi][2] = f2tf32(As[st][r0    ][kb + tig + 4]);
                af[mi][3] = f2tf32(As[st][r0 + 8][kb + tig + 4]);
            }
            uint32_t bf[8][2];
            #pragma unroll
            for (int ni = 0; ni < 8; ni++) {
                const int n0 = wn * 64 + ni * 8 + gid;
                bf[ni][0] = f2tf32(Bs[st][n0][kb + tig]);
                bf[ni][1] = f2tf32(Bs[st][n0][kb + tig + 4]);
            }
            #pragma unroll
            for (int mi = 0; mi < 2; mi++)
                #pragma unroll
                for (int ni = 0; ni < 8; ni++)
                    mma_tf32(acc[mi][ni], af[mi], bf[ni]);
        }
        __syncthreads();
    }

    // Epilogue: c0,c1 at (row, 2*tig), c2,c3 at (row+8, 2*tig)
    #pragma unroll
    for (int mi = 0; mi < 2; mi++) {
        const int row = crow0 + wm * 32 + mi * 16 + gid;
        #pragma unroll
        for (int ni = 0; ni < 8; ni++) {
            const int col = ccol0 + wn * 64 + ni * 8 + tig * 2;
            *reinterpret_cast<float2*>(&C[(size_t)row * DMODEL + col]) =
                make_float2(acc[mi][ni][0], acc[mi][ni][1]);
            *reinterpret_cast<float2*>(&C[(size_t)(row + 8) * DMODEL + col]) =
                make_float2(acc[mi][ni][2], acc[mi][ni][3]);
        }
    }
}

// Fused QKV: grid.x = 24 (3 weights x 8 col tiles), grid.y = 32 (row tiles)
__global__ __launch_bounds__(256) void qkv_gemm_mma(
    const float* __restrict__ x,
    const float* __restrict__ Wq,
    const float* __restrict__ Wk,
    const float* __restrict__ Wv)
{
    const int g  = blockIdx.x >> 3;
    const int bx = blockIdx.x & 7;
    const float* W; float* Cp;
    if      (g == 0) { W = Wq; Cp = g_q; }
    else if (g == 1) { W = Wk; Cp = g_k; }
    else             { W = Wv; Cp = g_v; }
    gemm_mma_tile(x, W, Cp, blockIdx.y * 128, bx * 128);
}

__global__ __launch_bounds__(256) void out_gemm_mma(
    const float* __restrict__ Wo, float* __restrict__ out)
{
    gemm_mma_tile(g_att, Wo, out, blockIdx.y * 128, blockIdx.x * 128);
}

// ---------------------------------------------------------------------------
// In-place RoPE on g_q, g_k
// ---------------------------------------------------------------------------
__global__ __launch_bounds__(256) void rope_kernel(
    const float* __restrict__ cosp, const float* __restrict__ sinp)
{
    const int idx = blockIdx.x * blockDim.x + threadIdx.x;
    const int d   = idx & 31;
    const int h   = (idx >> 5) & (NHEADS - 1);
    const int row = idx >> 9;
    const int s   = row & (SEQ - 1);

    const float c1 = cosp[s * HDIM + d];
    const float s1 = sinp[s * HDIM + d];
    const float c2 = cosp[s * HDIM + d + 32];
    const float s2 = sinp[s * HDIM + d + 32];

    const size_t base = (size_t)row * DMODEL + h * HDIM;

    const float q1 = g_q[base + d], q2 = g_q[base + d + 32];
    g_q[base + d]      = q1 * c1 - q2 * s1;
    g_q[base + d + 32] = q2 * c2 + q1 * s2;

    const float k1 = g_k[base + d], k2 = g_k[base + d + 32];
    g_k[base + d]      = k1 * c1 - k2 * s1;
    g_k[base + d + 32] = k2 * c2 + k1 * s2;
}

// ---------------------------------------------------------------------------
// Causal flash attention (proven R1 version)
// ---------------------------------------------------------------------------
__global__ __launch_bounds__(64) void attn_kernel()
{
    __shared__ float Ks[64][64];
    __shared__ float Vs[64][64];

    const int qt = blockIdx.x;
    const int bh = blockIdx.y;
    const int b  = bh >> 4, h = bh & 15;
    const int r  = threadIdx.x;
    const int qrow = qt * 64 + r;

    float qreg[64];
    {
        const float4* qp = reinterpret_cast<const float4*>(
            &g_q[(size_t)(b * SEQ + qrow) * DMODEL + h * HDIM]);
        #pragma unroll
        for (int i = 0; i < 16; i++) {
            float4 v = qp[i];
            qreg[4*i+0] = v.x * 0.125f; qreg[4*i+1] = v.y * 0.125f;
            qreg[4*i+2] = v.z * 0.125f; qreg[4*i+3] = v.w * 0.125f;
        }
    }

    float o[64];
    #pragma unroll
    for (int d = 0; d < 64; d++) o[d] = 0.f;
    float mval = -CUDART_INF_F, l = 0.f;

    for (int kt = 0; kt <= qt; kt++) {
        const int k0 = kt * 64;
        __syncthreads();
        {
            const float4* kp = reinterpret_cast<const float4*>(
                &g_k[(size_t)(b * SEQ + k0) * DMODEL + h * HDIM]);
            const float4* vp = reinterpret_cast<const float4*>(
                &g_v[(size_t)(b * SEQ + k0) * DMODEL + h * HDIM]);
            #pragma unroll
            for (int i = 0; i < 16; i++) {
                const int f = i * 64 + threadIdx.x;
                const int row = f >> 4, c = f & 15;
                const size_t src = (size_t)row * (DMODEL / 4) + c;
                *reinterpret_cast<float4*>(&Ks[row][c * 4]) = kp[src];
                *reinterpret_cast<float4*>(&Vs[row][c * 4]) = vp[src];
            }
        }
        __syncthreads();

        const bool diag = (kt == qt);
        for (int j0 = 0; j0 < 64; j0 += 16) {
            if (diag && j0 > r) break;
            float sj[16];
            float cmax = -CUDART_INF_F;
            #pragma unroll
            for (int j = 0; j < 16; j++) {
                const int jj = j0 + j;
                const float4* kr = reinterpret_cast<const float4*>(Ks[jj]);
                float sv = 0.f;
                #pragma unroll
                for (int d4 = 0; d4 < 16; d4++) {
                    float4 kv = kr[d4];
                    sv += qreg[4*d4+0] * kv.x + qreg[4*d4+1] * kv.y
                        + qreg[4*d4+2] * kv.z + qreg[4*d4+3] * kv.w;
                }
                if (diag && jj > r) sv = -CUDART_INF_F;
                sj[j] = sv;
                cmax = fmaxf(cmax, sv);
            }
            const float mnew = fmaxf(mval, cmax);
            const float corr = __expf(mval - mnew);
            l *= corr;
            #pragma unroll
            for (int d = 0; d < 64; d++) o[d] *= corr;
            #pragma unroll
            for (int j = 0; j < 16; j++) {
                const int jj = j0 + j;
                const float p = __expf(sj[j] - mnew);
                l += p;
                const float4* vr = reinterpret_cast<const float4*>(Vs[jj]);
                #pragma unroll
                for (int d4 = 0; d4 < 16; d4++) {
                    float4 vv = vr[d4];
                    o[4*d4+0] += p * vv.x; o[4*d4+1] += p * vv.y;
                    o[4*d4+2] += p * vv.z; o[4*d4+3] += p * vv.w;
                }
            }
            mval = mnew;
        }
    }

    const float inv = 1.f / l;
    float4* op = reinterpret_cast<float4*>(
        &g_att[(size_t)(b * SEQ + qrow) * DMODEL + h * HDIM]);
    #pragma unroll
    for (int i = 0; i < 16; i++)
        op[i] = make_float4(o[4*i+0] * inv, o[4*i+1] * inv,
                            o[4*i+2] * inv, o[4*i+3] * inv);
}

// ---------------------------------------------------------------------------
extern "C" void kernel_launch(void* const* d_in, const int* in_sizes, int n_in,
                              void* d_out, int out_size)
{
    const float* x    = (const float*)d_in[0];
    const float* cosp = (const float*)d_in[1];
    const float* sinp = (const float*)d_in[2];
    const float* Wq   = (const float*)d_in[3];
    const float* Wk   = (const float*)d_in[4];
    const float* Wv   = (const float*)d_in[5];
    const float* Wo   = (const float*)d_in[6];
    float* out = (float*)d_out;

    qkv_gemm_mma<<<dim3(24, 32), 256>>>(x, Wq, Wk, Wv);
    rope_kernel<<<(ROWS * NHEADS * 32) / 256, 256>>>(cosp, sinp);
    attn_kernel<<<dim3(SEQ / 64, BATCH * NHEADS), 64>>>();
    out_gemm_mma<<<dim3(8, 32), 256>>>(Wo, out);
}

// round 5
// speedup vs baseline: 4.3425x; 4.3425x over previous
#include <cuda_runtime.h>
#include <math_constants.h>
#include <cstdint>

#define BATCH 2
#define SEQ 2048
#define DMODEL 1024
#define NHEADS 16
#define HDIM 64
#define ROWS (BATCH*SEQ)   // 4096

// Scratch (allocation-free rule: __device__ globals). 16 MB each.
__device__ float g_q[(size_t)ROWS * DMODEL];
__device__ float g_k[(size_t)ROWS * DMODEL];
__device__ float g_v[(size_t)ROWS * DMODEL];
__device__ float g_att[(size_t)ROWS * DMODEL];

// ===========================================================================
// Helpers
// ===========================================================================
__device__ __forceinline__ uint32_t smem_u32(const void* p) {
    uint32_t a;
    asm("{ .reg .u64 t; cvta.to.shared.u64 t, %1; cvt.u32.u64 %0, t; }"
        : "=r"(a) : "l"(p));
    return a;
}
__device__ __forceinline__ void cp_async16(uint32_t dst, const void* src) {
    asm volatile("cp.async.cg.shared.global [%0], [%1], 16;"
                 :: "r"(dst), "l"(src));
}
#define CP_COMMIT() asm volatile("cp.async.commit_group;" ::: "memory")
#define CP_WAIT(n)  asm volatile("cp.async.wait_group %0;" :: "n"(n) : "memory")

__device__ __forceinline__ uint32_t f2tf32(float f) {
    uint32_t r;
    asm("cvt.rna.tf32.f32 %0, %1;" : "=r"(r) : "f"(f));
    return r;
}
__device__ __forceinline__ void mma_tf32(float c[4],
                                         const uint32_t a[4],
                                         const uint32_t b[2]) {
    asm volatile(
        "mma.sync.aligned.m16n8k8.row.col.f32.tf32.tf32.f32 "
        "{%0,%1,%2,%3}, {%4,%5,%6,%7}, {%8,%9}, {%0,%1,%2,%3};"
        : "+f"(c[0]), "+f"(c[1]), "+f"(c[2]), "+f"(c[3])
        : "r"(a[0]), "r"(a[1]), "r"(a[2]), "r"(a[3]), "r"(b[0]), "r"(b[1]));
}

// ===========================================================================
// tf32 mma.sync SGEMM_NT (unchanged from R3): C = A * Bw^T, 128x128 tiles
// ===========================================================================
constexpr int TCK    = 16;
constexpr int NCHUNK = DMODEL / TCK;       // 64
constexpr int SSTR   = 20;

__device__ __forceinline__ void gemm_mma_tile(
    const float* __restrict__ A, const float* __restrict__ Bw,
    float* __restrict__ C, int crow0, int ccol0)
{
    __shared__ float As[2][128][SSTR];
    __shared__ float Bs[2][128][SSTR];

    const int tid  = threadIdx.x;
    const int wid  = tid >> 5;
    const int lane = tid & 31;
    const int wm   = wid & 3;
    const int wn   = wid >> 2;
    const int gid  = lane >> 2;
    const int tig  = lane & 3;

    const float* gA = A  + (size_t)crow0 * DMODEL;
    const float* gB = Bw + (size_t)ccol0 * DMODEL;

    auto load_chunk = [&](int c) {
        const int st = c & 1;
        #pragma unroll
        for (int i = 0; i < 2; i++) {
            const int idx = i * 256 + tid;
            const int row = idx >> 2, c4 = idx & 3;
            const size_t g = (size_t)row * DMODEL + c * TCK + c4 * 4;
            cp_async16(smem_u32(&As[st][row][c4 * 4]), gA + g);
            cp_async16(smem_u32(&Bs[st][row][c4 * 4]), gB + g);
        }
        CP_COMMIT();
    };

    float acc[2][8][4];
    #pragma unroll
    for (int mi = 0; mi < 2; mi++)
        #pragma unroll
        for (int ni = 0; ni < 8; ni++)
            #pragma unroll
            for (int r = 0; r < 4; r++) acc[mi][ni][r] = 0.f;

    load_chunk(0);

    for (int c = 0; c < NCHUNK; c++) {
        if (c + 1 < NCHUNK) { load_chunk(c + 1); CP_WAIT(1); }
        else                { CP_WAIT(0); }
        __syncthreads();

        const int st = c & 1;
        #pragma unroll
        for (int ks = 0; ks < 2; ks++) {
            const int kb = ks * 8;
            uint32_t af[2][4];
            #pragma unroll
            for (int mi = 0; mi < 2; mi++) {
                const int r0 = wm * 32 + mi * 16 + gid;
                af[mi][0] = f2tf32(As[st][r0    ][kb + tig]);
                af[mi][1] = f2tf32(As[st][r0 + 8][kb + tig]);
                af[mi][2] = f2tf32(As[st][r0    ][kb + tig + 4]);
                af[mi][3] = f2tf32(As[st][r0 + 8][kb + tig + 4]);
            }
            uint32_t bf[8][2];
            #pragma unroll
            for (int ni = 0; ni < 8; ni++) {
                const int n0 = wn * 64 + ni * 8 + gid;
                bf[ni][0] = f2tf32(Bs[st][n0][kb + tig]);
                bf[ni][1] = f2tf32(Bs[st][n0][kb + tig + 4]);
            }
            #pragma unroll
            for (int mi = 0; mi < 2; mi++)
                #pragma unroll
                for (int ni = 0; ni < 8; ni++)
                    mma_tf32(acc[mi][ni], af[mi], bf[ni]);
        }
        __syncthreads();
    }

    #pragma unroll
    for (int mi = 0; mi < 2; mi++) {
        const int row = crow0 + wm * 32 + mi * 16 + gid;
        #pragma unroll
        for (int ni = 0; ni < 8; ni++) {
            const int col = ccol0 + wn * 64 + ni * 8 + tig * 2;
            *reinterpret_cast<float2*>(&C[(size_t)row * DMODEL + col]) =
                make_float2(acc[mi][ni][0], acc[mi][ni][1]);
            *reinterpret_cast<float2*>(&C[(size_t)(row + 8) * DMODEL + col]) =
                make_float2(acc[mi][ni][2], acc[mi][ni][3]);
        }
    }
}

__global__ __launch_bounds__(256) void qkv_gemm_mma(
    const float* __restrict__ x,
    const float* __restrict__ Wq,
    const float* __restrict__ Wk,
    const float* __restrict__ Wv)
{
    const int g  = blockIdx.x >> 3;
    const int bx = blockIdx.x & 7;
    const float* W; float* Cp;
    if      (g == 0) { W = Wq; Cp = g_q; }
    else if (g == 1) { W = Wk; Cp = g_k; }
    else             { W = Wv; Cp = g_v; }
    gemm_mma_tile(x, W, Cp, blockIdx.y * 128, bx * 128);
}

__global__ __launch_bounds__(256) void out_gemm_mma(
    const float* __restrict__ Wo, float* __restrict__ out)
{
    gemm_mma_tile(g_att, Wo, out, blockIdx.y * 128, blockIdx.x * 128);
}

// ---------------------------------------------------------------------------
// In-place RoPE on g_q, g_k
// ---------------------------------------------------------------------------
__global__ __launch_bounds__(256) void rope_kernel(
    const float* __restrict__ cosp, const float* __restrict__ sinp)
{
    const int idx = blockIdx.x * blockDim.x + threadIdx.x;
    const int d   = idx & 31;
    const int h   = (idx >> 5) & (NHEADS - 1);
    const int row = idx >> 9;
    const int s   = row & (SEQ - 1);

    const float c1 = cosp[s * HDIM + d];
    const float s1 = sinp[s * HDIM + d];
    const float c2 = cosp[s * HDIM + d + 32];
    const float s2 = sinp[s * HDIM + d + 32];

    const size_t base = (size_t)row * DMODEL + h * HDIM;

    const float q1 = g_q[base + d], q2 = g_q[base + d + 32];
    g_q[base + d]      = q1 * c1 - q2 * s1;
    g_q[base + d + 32] = q2 * c2 + q1 * s2;

    const float k1 = g_k[base + d], k2 = g_k[base + d + 32];
    g_k[base + d]      = k1 * c1 - k2 * s1;
    g_k[base + d + 32] = k2 * c2 + k1 * s2;
}

// ===========================================================================
// Tensor-core causal flash attention (tf32 mma.sync).
// Block: 256 threads (8 warps). Each block handles TWO 128-row q-tiles
// (qt = bx and 15-bx) of one (b,h)  ->  constant 34 k-tiles of work/block.
// Warp w owns q-rows [16w, 16w+16) of the tile. K/V 64x64 tiles
// double-buffered via cp.async, converted to tf32 in smem once per tile.
// P round-trips through smem for the PV mma. Online softmax in fragments.
// Smem strides: K/Q/P stride 68 (gid-indexed rows conflict-free),
// V stride 72 (tig-indexed rows conflict-free).
// ===========================================================================
#define AT_SK 68
#define AT_SV 72
#define AT_KFLOATS (64*AT_SK)               // 4352
#define AT_STAGE   (AT_KFLOATS + 64*AT_SV)  // 8960 floats per stage
#define AT_PS      (2*AT_STAGE)             // 17920: P/Q staging offset
#define AT_SMEM_BYTES ((AT_PS + 128*AT_SK) * 4)   // 106496

__global__ __launch_bounds__(256, 2) void attn_mma_kernel()
{
    extern __shared__ float sm[];
    const int tid = threadIdx.x, wid = tid >> 5, lane = tid & 31;
    const int gid = lane >> 2, tig = lane & 3;
    const int bh = blockIdx.y, b = bh >> 4, h = bh & 15;
    const float* Qg = g_q + (size_t)b * SEQ * DMODEL + h * HDIM;
    const float* Kg = g_k + (size_t)b * SEQ * DMODEL + h * HDIM;
    const float* Vg = g_v + (size_t)b * SEQ * DMODEL + h * HDIM;
    float*       Og = g_att + (size_t)b * SEQ * DMODEL + h * HDIM;

    for (int half = 0; half < 2; half++) {
        const int qt    = half ? (15 - (int)blockIdx.x) : (int)blockIdx.x;
        const int qrow0 = qt * 128;
        const int m0    = wid * 16;
        const int r0    = qrow0 + m0;          // warp's first global q-row

        __syncthreads();                       // Ps free from previous half
        // stage Q tile into Ps (coalesced), then build tf32 fragments
        for (int i = tid; i < 2048; i += 256) {
            const int row = i >> 4, c4 = (i & 15) * 4;
            *reinterpret_cast<float4*>(&sm[AT_PS + row * AT_SK + c4]) =
                *reinterpret_cast<const float4*>(
                    &Qg[(size_t)(qrow0 + row) * DMODEL + c4]);
        }
        __syncthreads();
        uint32_t qf[8][4];
        #pragma unroll
        for (int kb = 0; kb < 8; kb++) {
            const float* q0 = &sm[AT_PS + (m0 + gid) * AT_SK + kb * 8];
            const float* q1 = q0 + 8 * AT_SK;
            qf[kb][0] = f2tf32(q0[tig]     * 0.125f);
            qf[kb][1] = f2tf32(q1[tig]     * 0.125f);
            qf[kb][2] = f2tf32(q0[tig + 4] * 0.125f);
            qf[kb][3] = f2tf32(q1[tig + 4] * 0.125f);
        }
        __syncthreads();

        float oacc[8][4];
        #pragma unroll
        for (int n = 0; n < 8; n++)
            #pragma unroll
            for (int r = 0; r < 4; r++) oacc[n][r] = 0.f;
        float mr0 = -CUDART_INF_F, mr1 = -CUDART_INF_F;
        float lr0 = 0.f, lr1 = 0.f;
        const int ktmax = 2 * qt + 1;

        auto load_kv = [&](int kt, int st) {
            const float* Kp = Kg + (size_t)(kt * 64) * DMODEL;
            const float* Vp = Vg + (size_t)(kt * 64) * DMODEL;
            const uint32_t kd = smem_u32(&sm[st * AT_STAGE]);
            const uint32_t vd = kd + AT_KFLOATS * 4;
            #pragma unroll
            for (int i = 0; i < 4; i++) {
                const int idx = i * 256 + tid;            // [0,1024) float4
                const int row = idx >> 4, c4 = (idx & 15) * 4;
                const size_t g = (size_t)row * DMODEL + c4;
                cp_async16(kd + (row * AT_SK + c4) * 4, Kp + g);
                cp_async16(vd + (row * AT_SV + c4) * 4, Vp + g);
            }
            CP_COMMIT();
        };

        load_kv(0, 0);
        for (int kt = 0; kt <= ktmax; kt++) {
            const int st = kt & 1;
            const int k0 = kt * 64;
            if (kt < ktmax) { load_kv(kt + 1, st ^ 1); CP_WAIT(1); }
            else            { CP_WAIT(0); }
            __syncthreads();
            {   // convert K/V stage to tf32 bits in place (once per tile)
                uint32_t* sb = reinterpret_cast<uint32_t*>(&sm[st * AT_STAGE]);
                for (int i = tid; i < AT_STAGE; i += 256)
                    sb[i] = f2tf32(__uint_as_float(sb[i]));
            }
            __syncthreads();

            if (k0 <= r0 + 15) {              // warp has unmasked keys here
                const uint32_t* Ksm =
                    reinterpret_cast<const uint32_t*>(&sm[st * AT_STAGE]);
                const uint32_t* Vsm = Ksm + AT_KFLOATS;

                float sacc[8][4];
                #pragma unroll
                for (int n = 0; n < 8; n++)
                    #pragma unroll
                    for (int r = 0; r < 4; r++) sacc[n][r] = 0.f;

                #pragma unroll
                for (int kb = 0; kb < 8; kb++) {
                    #pragma unroll
                    for (int n = 0; n < 8; n++) {
                        const uint32_t* kr =
                            &Ksm[(n * 8 + gid) * AT_SK + kb * 8 + tig];
                        uint32_t bfr[2] = { kr[0], kr[4] };
                        mma_tf32(sacc[n], qf[kb], bfr);
                    }
                }
                if (k0 + 63 > r0) {           // diagonal tile: causal mask
                    const int row0 = r0 + gid, row1 = row0 + 8;
                    #pragma unroll
                    for (int n = 0; n < 8; n++) {
                        const int c = k0 + n * 8 + 2 * tig;
                        if (c     > row0) sacc[n][0] = -CUDART_INF_F;
                        if (c + 1 > row0) sacc[n][1] = -CUDART_INF_F;
                        if (c     > row1) sacc[n][2] = -CUDART_INF_F;
                        if (c + 1 > row1) sacc[n][3] = -CUDART_INF_F;
                    }
                }
                float cm0 = -CUDART_INF_F, cm1 = -CUDART_INF_F;
                #pragma unroll
                for (int n = 0; n < 8; n++) {
                    cm0 = fmaxf(cm0, fmaxf(sacc[n][0], sacc[n][1]));
                    cm1 = fmaxf(cm1, fmaxf(sacc[n][2], sacc[n][3]));
                }
                cm0 = fmaxf(cm0, __shfl_xor_sync(0xffffffffu, cm0, 1));
                cm0 = fmaxf(cm0, __shfl_xor_sync(0xffffffffu, cm0, 2));
                cm1 = fmaxf(cm1, __shfl_xor_sync(0xffffffffu, cm1, 1));
                cm1 = fmaxf(cm1, __shfl_xor_sync(0xffffffffu, cm1, 2));
                const float mn0 = fmaxf(mr0, cm0), mn1 = fmaxf(mr1, cm1);
                const float co0 = __expf(mr0 - mn0), co1 = __expf(mr1 - mn1);
                float ps0 = 0.f, ps1 = 0.f;
                uint32_t* Pw =
                    reinterpret_cast<uint32_t*>(&sm[AT_PS + m0 * AT_SK]);
                #pragma unroll
                for (int n = 0; n < 8; n++) {
                    const float p00 = __expf(sacc[n][0] - mn0);
                    const float p01 = __expf(sacc[n][1] - mn0);
                    const float p10 = __expf(sacc[n][2] - mn1);
                    const float p11 = __expf(sacc[n][3] - mn1);
                    ps0 += p00 + p01; ps1 += p10 + p11;
                    *reinterpret_cast<uint2*>(
                        &Pw[gid * AT_SK + n * 8 + 2 * tig]) =
                        make_uint2(f2tf32(p00), f2tf32(p01));
                    *reinterpret_cast<uint2*>(
                        &Pw[(gid + 8) * AT_SK + n * 8 + 2 * tig]) =
                        make_uint2(f2tf32(p10), f2tf32(p11));
                    oacc[n][0] *= co0; oacc[n][1] *= co0;
                    oacc[n][2] *= co1; oacc[n][3] *= co1;
                }
                ps0 += __shfl_xor_sync(0xffffffffu, ps0, 1);
                ps0 += __shfl_xor_sync(0xffffffffu, ps0, 2);
                ps1 += __shfl_xor_sync(0xffffffffu, ps1, 1);
                ps1 += __shfl_xor_sync(0xffffffffu, ps1, 2);
                lr0 = lr0 * co0 + ps0;  lr1 = lr1 * co1 + ps1;
                mr0 = mn0;  mr1 = mn1;
                __syncwarp();
                #pragma unroll
                for (int kb = 0; kb < 8; kb++) {
                    const uint32_t* pr = &Pw[gid * AT_SK + kb * 8 + tig];
                    uint32_t pf[4] = { pr[0], pr[8 * AT_SK],
                                       pr[4], pr[8 * AT_SK + 4] };
                    #pragma unroll
                    for (int n = 0; n < 8; n++) {
                        const uint32_t* vr =
                            &Vsm[(kb * 8 + tig) * AT_SV + n * 8 + gid];
                        uint32_t vb2[2] = { vr[0], vr[4 * AT_SV] };
                        mma_tf32(oacc[n], pf, vb2);
                    }
                }
            }
            __syncthreads();
        }

        const float i0 = 1.f / lr0, i1 = 1.f / lr1;
        #pragma unroll
        for (int n = 0; n < 8; n++) {
            const int col = n * 8 + 2 * tig;
            *reinterpret_cast<float2*>(
                &Og[(size_t)(r0 + gid) * DMODEL + col]) =
                make_float2(oacc[n][0] * i0, oacc[n][1] * i0);
            *reinterpret_cast<float2*>(
                &Og[(size_t)(r0 + gid + 8) * DMODEL + col]) =
                make_float2(oacc[n][2] * i1, oacc[n][3] * i1);
        }
    }
}

// ---------------------------------------------------------------------------
extern "C" void kernel_launch(void* const* d_in, const int* in_sizes, int n_in,
                              void* d_out, int out_size)
{
    const float* x    = (const float*)d_in[0];
    const float* cosp = (const float*)d_in[1];
    const float* sinp = (const float*)d_in[2];
    const float* Wq   = (const float*)d_in[3];
    const float* Wk   = (const float*)d_in[4];
    const float* Wv   = (const float*)d_in[5];
    const float* Wo   = (const float*)d_in[6];
    float* out = (float*)d_out;

    cudaFuncSetAttribute(attn_mma_kernel,
        cudaFuncAttributeMaxDynamicSharedMemorySize, AT_SMEM_BYTES);

    qkv_gemm_mma<<<dim3(24, 32), 256>>>(x, Wq, Wk, Wv);
    rope_kernel<<<(ROWS * NHEADS * 32) / 256, 256>>>(cosp, sinp);
    attn_mma_kernel<<<dim3(8, 32), 256, AT_SMEM_BYTES>>>();
    out_gemm_mma<<<dim3(8, 32), 256>>>(Wo, out);
}

// round 10
// speedup vs baseline: 4.5828x; 1.0553x over previous
#include <cuda_runtime.h>
#include <math_constants.h>
#include <cstdint>

#define BATCH 2
#define SEQ 2048
#define DMODEL 1024
#define NHEADS 16
#define HDIM 64
#define ROWS (BATCH*SEQ)   // 4096

// Scratch (allocation-free rule: __device__ globals).
__device__ float    g_q[(size_t)ROWS * DMODEL];
__device__ float    g_k[(size_t)ROWS * DMODEL];
__device__ float    g_v[(size_t)ROWS * DMODEL];
__device__ float    g_att[(size_t)ROWS * DMODEL];
__device__ uint32_t g_xc[(size_t)ROWS * DMODEL];          // tf32 bits of x
__device__ uint32_t g_wc[(size_t)4 * DMODEL * DMODEL];    // tf32 bits of Wq,Wk,Wv,Wo

// ===========================================================================
// Helpers
// ===========================================================================
__device__ __forceinline__ uint32_t smem_u32(const void* p) {
    uint32_t a;
    asm("{ .reg .u64 t; cvta.to.shared.u64 t, %1; cvt.u32.u64 %0, t; }"
        : "=r"(a) : "l"(p));
    return a;
}
__device__ __forceinline__ void cp_async16(uint32_t dst, const void* src) {
    asm volatile("cp.async.cg.shared.global [%0], [%1], 16;"
                 :: "r"(dst), "l"(src));
}
#define CP_COMMIT() asm volatile("cp.async.commit_group;" ::: "memory")
#define CP_WAIT(n)  asm volatile("cp.async.wait_group %0;" :: "n"(n) : "memory")

__device__ __forceinline__ uint32_t f2tf32(float f) {
    uint32_t r;
    asm("cvt.rna.tf32.f32 %0, %1;" : "=r"(r) : "f"(f));
    return r;
}
__device__ __forceinline__ void mma_tf32(float c[4],
                                         const uint32_t a[4],
                                         const uint32_t b[2]) {
    asm volatile(
        "mma.sync.aligned.m16n8k8.row.col.f32.tf32.tf32.f32 "
        "{%0,%1,%2,%3}, {%4,%5,%6,%7}, {%8,%9}, {%0,%1,%2,%3};"
        : "+f"(c[0]), "+f"(c[1]), "+f"(c[2]), "+f"(c[3])
        : "r"(a[0]), "r"(a[1]), "r"(a[2]), "r"(a[3]), "r"(b[0]), "r"(b[1]));
}

// ===========================================================================
// Pre-pass: round x + all weights to tf32 bits once.
// 2M float4 slots: [0,1M) = x, then 256K per weight.
// ===========================================================================
__global__ __launch_bounds__(256) void convert_tf32_kernel(
    const float* __restrict__ x,  const float* __restrict__ wq,
    const float* __restrict__ wk, const float* __restrict__ wv,
    const float* __restrict__ wo)
{
    const int idx = blockIdx.x * 256 + threadIdx.x;   // float4 index
    const float* src;
    uint32_t*    dst;
    if (idx < (1 << 20)) {
        src = x + (size_t)idx * 4;
        dst = g_xc + (size_t)idx * 4;
    } else {
        const int j   = idx - (1 << 20);
        const int w   = j >> 18;                      // 256K float4 per W
        const int off = j & ((1 << 18) - 1);
        const float* ws = (w == 0) ? wq : (w == 1) ? wk : (w == 2) ? wv : wo;
        src = ws + (size_t)off * 4;
        dst = g_wc + (size_t)w * DMODEL * DMODEL + (size_t)off * 4;
    }
    const float4 v = *reinterpret_cast<const float4*>(src);
    *reinterpret_cast<uint4*>(dst) =
        make_uint4(f2tf32(v.x), f2tf32(v.y), f2tf32(v.z), f2tf32(v.w));
}

// ===========================================================================
// tf32 mma.sync SGEMM_NT on pre-rounded bits: C = A * Bw^T, 128x128 tiles.
// No cvt in the mainloop. Optional tf32-rounding of C (for V).
// ===========================================================================
constexpr int TCK    = 16;
constexpr int NCHUNK = DMODEL / TCK;       // 64
constexpr int SSTR   = 20;

__device__ __forceinline__ void gemm_mma_tile(
    const uint32_t* __restrict__ A, const uint32_t* __restrict__ Bw,
    float* __restrict__ C, int crow0, int ccol0, bool roundC)
{
    __shared__ uint32_t As[2][128][SSTR];
    __shared__ uint32_t Bs[2][128][SSTR];

    const int tid  = threadIdx.x;
    const int wid  = tid >> 5;
    const int lane = tid & 31;
    const int wm   = wid & 3;
    const int wn   = wid >> 2;
    const int gid  = lane >> 2;
    const int tig  = lane & 3;

    const uint32_t* gA = A  + (size_t)crow0 * DMODEL;
    const uint32_t* gB = Bw + (size_t)ccol0 * DMODEL;

    auto load_chunk = [&](int c) {
        const int st = c & 1;
        #pragma unroll
        for (int i = 0; i < 2; i++) {
            const int idx = i * 256 + tid;
            const int row = idx >> 2, c4 = idx & 3;
            const size_t g = (size_t)row * DMODEL + c * TCK + c4 * 4;
            cp_async16(smem_u32(&As[st][row][c4 * 4]), gA + g);
            cp_async16(smem_u32(&Bs[st][row][c4 * 4]), gB + g);
        }
        CP_COMMIT();
    };

    float acc[2][8][4];
    #pragma unroll
    for (int mi = 0; mi < 2; mi++)
        #pragma unroll
        for (int ni = 0; ni < 8; ni++)
            #pragma unroll
            for (int r = 0; r < 4; r++) acc[mi][ni][r] = 0.f;

    load_chunk(0);

    for (int c = 0; c < NCHUNK; c++) {
        if (c + 1 < NCHUNK) { load_chunk(c + 1); CP_WAIT(1); }
        else                { CP_WAIT(0); }
        __syncthreads();

        const int st = c & 1;
        #pragma unroll
        for (int ks = 0; ks < 2; ks++) {
            const int kb = ks * 8;
            uint32_t af[2][4];
            #pragma unroll
            for (int mi = 0; mi < 2; mi++) {
                const int r0 = wm * 32 + mi * 16 + gid;
                af[mi][0] = As[st][r0    ][kb + tig];
                af[mi][1] = As[st][r0 + 8][kb + tig];
                af[mi][2] = As[st][r0    ][kb + tig + 4];
                af[mi][3] = As[st][r0 + 8][kb + tig + 4];
            }
            uint32_t bf[8][2];
            #pragma unroll
            for (int ni = 0; ni < 8; ni++) {
                const int n0 = wn * 64 + ni * 8 + gid;
                bf[ni][0] = Bs[st][n0][kb + tig];
                bf[ni][1] = Bs[st][n0][kb + tig + 4];
            }
            #pragma unroll
            for (int mi = 0; mi < 2; mi++)
                #pragma unroll
                for (int ni = 0; ni < 8; ni++)
                    mma_tf32(acc[mi][ni], af[mi], bf[ni]);
        }
        __syncthreads();
    }

    #pragma unroll
    for (int mi = 0; mi < 2; mi++) {
        const int row = crow0 + wm * 32 + mi * 16 + gid;
        #pragma unroll
        for (int ni = 0; ni < 8; ni++) {
            const int col = ccol0 + wn * 64 + ni * 8 + tig * 2;
            float v0 = acc[mi][ni][0], v1 = acc[mi][ni][1];
            float v2 = acc[mi][ni][2], v3 = acc[mi][ni][3];
            if (roundC) {
                v0 = __uint_as_float(f2tf32(v0));
                v1 = __uint_as_float(f2tf32(v1));
                v2 = __uint_as_float(f2tf32(v2));
                v3 = __uint_as_float(f2tf32(v3));
            }
            *reinterpret_cast<float2*>(&C[(size_t)row * DMODEL + col]) =
                make_float2(v0, v1);
            *reinterpret_cast<float2*>(&C[(size_t)(row + 8) * DMODEL + col]) =
                make_float2(v2, v3);
        }
    }
}

__global__ __launch_bounds__(256) void qkv_gemm_mma()
{
    const int g  = blockIdx.x >> 3;
    const int bx = blockIdx.x & 7;
    float* Cp = (g == 0) ? g_q : (g == 1) ? g_k : g_v;
    gemm_mma_tile(g_xc, g_wc + (size_t)g * DMODEL * DMODEL, Cp,
                  blockIdx.y * 128, bx * 128, g == 2 /* round V */);
}

__global__ __launch_bounds__(256) void out_gemm_mma(float* __restrict__ out)
{
    gemm_mma_tile(reinterpret_cast<const uint32_t*>(g_att),
                  g_wc + (size_t)3 * DMODEL * DMODEL, out,
                  blockIdx.y * 128, blockIdx.x * 128, false);
}

// ---------------------------------------------------------------------------
// In-place RoPE on g_q, g_k. Writes tf32-rounded values; Q pre-scaled by 1/8
// (power of 2 -> commutes exactly with tf32 rounding).
// ---------------------------------------------------------------------------
__global__ __launch_bounds__(256) void rope_kernel(
    const float* __restrict__ cosp, const float* __restrict__ sinp)
{
    const int idx = blockIdx.x * blockDim.x + threadIdx.x;
    const int d   = idx & 31;
    const int h   = (idx >> 5) & (NHEADS - 1);
    const int row = idx >> 9;
    const int s   = row & (SEQ - 1);

    const float c1 = cosp[s * HDIM + d];
    const float s1 = sinp[s * HDIM + d];
    const float c2 = cosp[s * HDIM + d + 32];
    const float s2 = sinp[s * HDIM + d + 32];

    const size_t base = (size_t)row * DMODEL + h * HDIM;

    const float q1 = g_q[base + d], q2 = g_q[base + d + 32];
    g_q[base + d]      = __uint_as_float(f2tf32((q1 * c1 - q2 * s1) * 0.125f));
    g_q[base + d + 32] = __uint_as_float(f2tf32((q2 * c2 + q1 * s2) * 0.125f));

    const float k1 = g_k[base + d], k2 = g_k[base + d + 32];
    g_k[base + d]      = __uint_as_float(f2tf32(k1 * c1 - k2 * s1));
    g_k[base + d + 32] = __uint_as_float(f2tf32(k2 * c2 + k1 * s2));
}

// ===========================================================================
// Tensor-core causal flash attention (tf32 mma.sync), operands pre-rounded.
// Block: 256 threads (8 warps); two paired 128-row q-tiles (qt, 15-qt).
// K/V 64x64 tiles double-buffered via cp.async (bits already tf32).
// P round-trips through smem for the PV mma. Online softmax in fragments.
// ===========================================================================
#define AT_SK 68
#define AT_SV 72
#define AT_KFLOATS (64*AT_SK)               // 4352
#define AT_STAGE   (AT_KFLOATS + 64*AT_SV)  // 8960 floats per stage
#define AT_PS      (2*AT_STAGE)             // P/Q staging offset
#define AT_SMEM_BYTES ((AT_PS + 128*AT_SK) * 4)   // 106496

__global__ __launch_bounds__(256, 2) void attn_mma_kernel()
{
    extern __shared__ float sm[];
    const int tid = threadIdx.x, wid = tid >> 5, lane = tid & 31;
    const int gid = lane >> 2, tig = lane & 3;
    const int bh = blockIdx.y, b = bh >> 4, h = bh & 15;
    const float* Qg = g_q + (size_t)b * SEQ * DMODEL + h * HDIM;
    const float* Kg = g_k + (size_t)b * SEQ * DMODEL + h * HDIM;
    const float* Vg = g_v + (size_t)b * SEQ * DMODEL + h * HDIM;
    float*       Og = g_att + (size_t)b * SEQ * DMODEL + h * HDIM;

    for (int half = 0; half < 2; half++) {
        const int qt    = half ? (15 - (int)blockIdx.x) : (int)blockIdx.x;
        const int qrow0 = qt * 128;
        const int m0    = wid * 16;
        const int r0    = qrow0 + m0;

        __syncthreads();                       // Ps free from previous half
        for (int i = tid; i < 2048; i += 256) {
            const int row = i >> 4, c4 = (i & 15) * 4;
            *reinterpret_cast<float4*>(&sm[AT_PS + row * AT_SK + c4]) =
                *reinterpret_cast<const float4*>(
                    &Qg[(size_t)(qrow0 + row) * DMODEL + c4]);
        }
        __syncthreads();
        uint32_t qf[8][4];
        #pragma unroll
        for (int kb = 0; kb < 8; kb++) {
            const uint32_t* q0 = reinterpret_cast<const uint32_t*>(
                &sm[AT_PS + (m0 + gid) * AT_SK + kb * 8]);
            const uint32_t* q1 = q0 + 8 * AT_SK;
            qf[kb][0] = q0[tig];
            qf[kb][1] = q1[tig];
            qf[kb][2] = q0[tig + 4];
            qf[kb][3] = q1[tig + 4];
        }
        __syncthreads();

        float oacc[8][4];
        #pragma unroll
        for (int n = 0; n < 8; n++)
            #pragma unroll
            for (int r = 0; r < 4; r++) oacc[n][r] = 0.f;
        float mr0 = -CUDART_INF_F, mr1 = -CUDART_INF_F;
        float lr0 = 0.f, lr1 = 0.f;
        const int ktmax = 2 * qt + 1;

        auto load_kv = [&](int kt, int st) {
            const float* Kp = Kg + (size_t)(kt * 64) * DMODEL;
            const float* Vp = Vg + (size_t)(kt * 64) * DMODEL;
            const uint32_t kd = smem_u32(&sm[st * AT_STAGE]);
            const uint32_t vd = kd + AT_KFLOATS * 4;
            #pragma unroll
            for (int i = 0; i < 4; i++) {
                const int idx = i * 256 + tid;
                const int row = idx >> 4, c4 = (idx & 15) * 4;
                const size_t g = (size_t)row * DMODEL + c4;
                cp_async16(kd + (row * AT_SK + c4) * 4, Kp + g);
                cp_async16(vd + (row * AT_SV + c4) * 4, Vp + g);
            }
            CP_COMMIT();
        };

        load_kv(0, 0);
        for (int kt = 0; kt <= ktmax; kt++) {
            const int st = kt & 1;
            const int k0 = kt * 64;
            if (kt < ktmax) { load_kv(kt + 1, st ^ 1); CP_WAIT(1); }
            else            { CP_WAIT(0); }
            __syncthreads();

            if (k0 <= r0 + 15) {
                const uint32_t* Ksm =
                    reinterpret_cast<const uint32_t*>(&sm[st * AT_STAGE]);
                const uint32_t* Vsm = Ksm + AT_KFLOATS;

                float sacc[8][4];
                #pragma unroll
                for (int n = 0; n < 8; n++)
                    #pragma unroll
                    for (int r = 0; r < 4; r++) sacc[n][r] = 0.f;

                #pragma unroll
                for (int kb = 0; kb < 8; kb++) {
                    #pragma unroll
                    for (int n = 0; n < 8; n++) {
                        const uint32_t* kr =
                            &Ksm[(n * 8 + gid) * AT_SK + kb * 8 + tig];
                        uint32_t bfr[2] = { kr[0], kr[4] };
                        mma_tf32(sacc[n], qf[kb], bfr);
                    }
                }
                if (k0 + 63 > r0) {
                    const int row0 = r0 + gid, row1 = row0 + 8;
                    #pragma unroll
                    for (int n = 0; n < 8; n++) {
                        const int c = k0 + n * 8 + 2 * tig;
                        if (c     > row0) sacc[n][0] = -CUDART_INF_F;
                        if (c + 1 > row0) sacc[n][1] = -CUDART_INF_F;
                        if (c     > row1) sacc[n][2] = -CUDART_INF_F;
                        if (c + 1 > row1) sacc[n][3] = -CUDART_INF_F;
                    }
                }
                float cm0 = -CUDART_INF_F, cm1 = -CUDART_INF_F;
                #pragma unroll
                for (int n = 0; n < 8; n++) {
                    cm0 = fmaxf(cm0, fmaxf(sacc[n][0], sacc[n][1]));
                    cm1 = fmaxf(cm1, fmaxf(sacc[n][2], sacc[n][3]));
                }
                cm0 = fmaxf(cm0, __shfl_xor_sync(0xffffffffu, cm0, 1));
                cm0 = fmaxf(cm0, __shfl_xor_sync(0xffffffffu, cm0, 2));
                cm1 = fmaxf(cm1, __shfl_xor_sync(0xffffffffu, cm1, 1));
                cm1 = fmaxf(cm1, __shfl_xor_sync(0xffffffffu, cm1, 2));
                const float mn0 = fmaxf(mr0, cm0), mn1 = fmaxf(mr1, cm1);
                const float co0 = __expf(mr0 - mn0), co1 = __expf(mr1 - mn1);
                float ps0 = 0.f, ps1 = 0.f;
                uint32_t* Pw =
                    reinterpret_cast<uint32_t*>(&sm[AT_PS + m0 * AT_SK]);
                #pragma unroll
                for (int n = 0; n < 8; n++) {
                    const float p00 = __expf(sacc[n][0] - mn0);
                    const float p01 = __expf(sacc[n][1] - mn0);
                    const float p10 = __expf(sacc[n][2] - mn1);
                    const float p11 = __expf(sacc[n][3] - mn1);
                    ps0 += p00 + p01; ps1 += p10 + p11;
                    *reinterpret_cast<uint2*>(
                        &Pw[gid * AT_SK + n * 8 + 2 * tig]) =
                        make_uint2(f2tf32(p00), f2tf32(p01));
                    *reinterpret_cast<uint2*>(
                        &Pw[(gid + 8) * AT_SK + n * 8 + 2 * tig]) =
                        make_uint2(f2tf32(p10), f2tf32(p11));
                    oacc[n][0] *= co0; oacc[n][1] *= co0;
                    oacc[n][2] *= co1; oacc[n][3] *= co1;
                }
                ps0 += __shfl_xor_sync(0xffffffffu, ps0, 1);
                ps0 += __shfl_xor_sync(0xffffffffu, ps0, 2);
                ps1 += __shfl_xor_sync(0xffffffffu, ps1, 1);
                ps1 += __shfl_xor_sync(0xffffffffu, ps1, 2);
                lr0 = lr0 * co0 + ps0;  lr1 = lr1 * co1 + ps1;
                mr0 = mn0;  mr1 = mn1;
                __syncwarp();
                #pragma unroll
                for (int kb = 0; kb < 8; kb++) {
                    const uint32_t* pr = &Pw[gid * AT_SK + kb * 8 + tig];
                    uint32_t pf[4] = { pr[0], pr[8 * AT_SK],
                                       pr[4], pr[8 * AT_SK + 4] };
                    #pragma unroll
                    for (int n = 0; n < 8; n++) {
                        const uint32_t* vr =
                            &Vsm[(kb * 8 + tig) * AT_SV + n * 8 + gid];
                        uint32_t vb2[2] = { vr[0], vr[4 * AT_SV] };
                        mma_tf32(oacc[n], pf, vb2);
                    }
                }
            }
            __syncthreads();
        }

        // Write O tf32-rounded so out_gemm consumes bits directly.
        const float i0 = 1.f / lr0, i1 = 1.f / lr1;
        #pragma unroll
        for (int n = 0; n < 8; n++) {
            const int col = n * 8 + 2 * tig;
            *reinterpret_cast<float2*>(
                &Og[(size_t)(r0 + gid) * DMODEL + col]) =
                make_float2(__uint_as_float(f2tf32(oacc[n][0] * i0)),
                            __uint_as_float(f2tf32(oacc[n][1] * i0)));
            *reinterpret_cast<float2*>(
                &Og[(size_t)(r0 + gid + 8) * DMODEL + col]) =
                make_float2(__uint_as_float(f2tf32(oacc[n][2] * i1)),
                            __uint_as_float(f2tf32(oacc[n][3] * i1)));
        }
    }
}

// ---------------------------------------------------------------------------
extern "C" void kernel_launch(void* const* d_in, const int* in_sizes, int n_in,
                              void* d_out, int out_size)
{
    const float* x    = (const float*)d_in[0];
    const float* cosp = (const float*)d_in[1];
    const float* sinp = (const float*)d_in[2];
    const float* Wq   = (const float*)d_in[3];
    const float* Wk   = (const float*)d_in[4];
    const float* Wv   = (const float*)d_in[5];
    const float* Wo   = (const float*)d_in[6];
    float* out = (float*)d_out;

    cudaFuncSetAttribute(attn_mma_kernel,
        cudaFuncAttributeMaxDynamicSharedMemorySize, AT_SMEM_BYTES);

    convert_tf32_kernel<<<8192, 256>>>(x, Wq, Wk, Wv, Wo);
    qkv_gemm_mma<<<dim3(24, 32), 256>>>();
    rope_kernel<<<(ROWS * NHEADS * 32) / 256, 256>>>(cosp, sinp);
    attn_mma_kernel<<<dim3(8, 32), 256, AT_SMEM_BYTES>>>();
    out_gemm_mma<<<dim3(8, 32), 256>>>(out);
}

// round 11
// speedup vs baseline: 4.8529x; 1.0589x over previous
#include <cuda_runtime.h>
#include <math_constants.h>
#include <cstdint>

#define BATCH 2
#define SEQ 2048
#define DMODEL 1024
#define NHEADS 16
#define HDIM 64
#define ROWS (BATCH*SEQ)   // 4096

// Scratch (allocation-free rule: __device__ globals).
__device__ float    g_q[(size_t)ROWS * DMODEL];
__device__ float    g_k[(size_t)ROWS * DMODEL];
__device__ float    g_v[(size_t)ROWS * DMODEL];
__device__ float    g_att[(size_t)ROWS * DMODEL];
__device__ uint32_t g_xc[(size_t)ROWS * DMODEL];          // tf32 bits of x
__device__ uint32_t g_wc[(size_t)4 * DMODEL * DMODEL];    // tf32 bits of Wq,Wk,Wv,Wo

// ===========================================================================
// Helpers
// ===========================================================================
__device__ __forceinline__ uint32_t smem_u32(const void* p) {
    uint32_t a;
    asm("{ .reg .u64 t; cvta.to.shared.u64 t, %1; cvt.u32.u64 %0, t; }"
        : "=r"(a) : "l"(p));
    return a;
}
__device__ __forceinline__ void cp_async16(uint32_t dst, const void* src) {
    asm volatile("cp.async.cg.shared.global [%0], [%1], 16;"
                 :: "r"(dst), "l"(src));
}
#define CP_COMMIT() asm volatile("cp.async.commit_group;" ::: "memory")
#define CP_WAIT(n)  asm volatile("cp.async.wait_group %0;" :: "n"(n) : "memory")

__device__ __forceinline__ uint32_t f2tf32(float f) {
    uint32_t r;
    asm("cvt.rna.tf32.f32 %0, %1;" : "=r"(r) : "f"(f));
    return r;
}
__device__ __forceinline__ void mma_tf32(float c[4],
                                         const uint32_t a[4],
                                         const uint32_t b[2]) {
    asm volatile(
        "mma.sync.aligned.m16n8k8.row.col.f32.tf32.tf32.f32 "
        "{%0,%1,%2,%3}, {%4,%5,%6,%7}, {%8,%9}, {%0,%1,%2,%3};"
        : "+f"(c[0]), "+f"(c[1]), "+f"(c[2]), "+f"(c[3])
        : "r"(a[0]), "r"(a[1]), "r"(a[2]), "r"(a[3]), "r"(b[0]), "r"(b[1]));
}

// ===========================================================================
// Pre-pass: round x + all weights to tf32 bits once.
// 2M float4 slots: [0,1M) = x, then 256K per weight.
// ===========================================================================
__global__ __launch_bounds__(256) void convert_tf32_kernel(
    const float* __restrict__ x,  const float* __restrict__ wq,
    const float* __restrict__ wk, const float* __restrict__ wv,
    const float* __restrict__ wo)
{
    const int idx = blockIdx.x * 256 + threadIdx.x;   // float4 index
    const float* src;
    uint32_t*    dst;
    if (idx < (1 << 20)) {
        src = x + (size_t)idx * 4;
        dst = g_xc + (size_t)idx * 4;
    } else {
        const int j   = idx - (1 << 20);
        const int w   = j >> 18;                      // 256K float4 per W
        const int off = j & ((1 << 18) - 1);
        const float* ws = (w == 0) ? wq : (w == 1) ? wk : (w == 2) ? wv : wo;
        src = ws + (size_t)off * 4;
        dst = g_wc + (size_t)w * DMODEL * DMODEL + (size_t)off * 4;
    }
    const float4 v = *reinterpret_cast<const float4*>(src);
    *reinterpret_cast<uint4*>(dst) =
        make_uint4(f2tf32(v.x), f2tf32(v.y), f2tf32(v.z), f2tf32(v.w));
}

// ===========================================================================
// tf32 mma.sync SGEMM_NT on pre-rounded bits: C = A * Bw^T, 128x128 block
// tile, 4 warps (2x2), warp tile 64x64, 128 threads. BK=16 double-buffered.
// Epilogue modes: 0 = plain store, 1 = tf32-round (V),
//                 2 = RoPE + 1/8 scale + round (Q), 3 = RoPE + round (K).
// Warp n-band is 64 cols = exactly one head -> RoPE pairs (d, d+32) live in
// acc[mi][ni] / acc[mi][ni+4] of the SAME thread.
// ===========================================================================
constexpr int G_BK     = 16;
constexpr int G_NCHUNK = DMODEL / G_BK;    // 64
constexpr int G_SSTR   = 20;

__device__ __forceinline__ void gemm_tile_w64(
    const uint32_t* __restrict__ A, const uint32_t* __restrict__ Bw,
    float* __restrict__ C, int crow0, int ccol0, int mode,
    const float* __restrict__ cosp, const float* __restrict__ sinp)
{
    __shared__ uint32_t As[2][128][G_SSTR];
    __shared__ uint32_t Bs[2][128][G_SSTR];

    const int tid  = threadIdx.x;        // 0..127
    const int wid  = tid >> 5;
    const int lane = tid & 31;
    const int wm   = wid & 1;            // 64-row band
    const int wn   = wid >> 1;           // 64-col band
    const int gid  = lane >> 2;          // 0..7
    const int tig  = lane & 3;           // 0..3

    const uint32_t* gA = A  + (size_t)crow0 * DMODEL;
    const uint32_t* gB = Bw + (size_t)ccol0 * DMODEL;

    auto load_chunk = [&](int c) {
        const int st = c & 1;
        #pragma unroll
        for (int i = 0; i < 4; i++) {
            const int idx = i * 128 + tid;     // [0,512) float4 slots
            const int row = idx >> 2, c4 = idx & 3;
            const size_t g = (size_t)row * DMODEL + c * G_BK + c4 * 4;
            cp_async16(smem_u32(&As[st][row][c4 * 4]), gA + g);
            cp_async16(smem_u32(&Bs[st][row][c4 * 4]), gB + g);
        }
        CP_COMMIT();
    };

    float acc[4][8][4];
    #pragma unroll
    for (int mi = 0; mi < 4; mi++)
        #pragma unroll
        for (int ni = 0; ni < 8; ni++)
            #pragma unroll
            for (int r = 0; r < 4; r++) acc[mi][ni][r] = 0.f;

    load_chunk(0);

    for (int c = 0; c < G_NCHUNK; c++) {
        if (c + 1 < G_NCHUNK) { load_chunk(c + 1); CP_WAIT(1); }
        else                  { CP_WAIT(0); }
        __syncthreads();

        const int st = c & 1;
        #pragma unroll
        for (int ks = 0; ks < 2; ks++) {
            const int kb = ks * 8;
            uint32_t af[4][4];
            #pragma unroll
            for (int mi = 0; mi < 4; mi++) {
                const int r0 = wm * 64 + mi * 16 + gid;
                af[mi][0] = As[st][r0    ][kb + tig];
                af[mi][1] = As[st][r0 + 8][kb + tig];
                af[mi][2] = As[st][r0    ][kb + tig + 4];
                af[mi][3] = As[st][r0 + 8][kb + tig + 4];
            }
            uint32_t bf[8][2];
            #pragma unroll
            for (int ni = 0; ni < 8; ni++) {
                const int n0 = wn * 64 + ni * 8 + gid;
                bf[ni][0] = Bs[st][n0][kb + tig];
                bf[ni][1] = Bs[st][n0][kb + tig + 4];
            }
            #pragma unroll
            for (int mi = 0; mi < 4; mi++)
                #pragma unroll
                for (int ni = 0; ni < 8; ni++)
                    mma_tf32(acc[mi][ni], af[mi], bf[ni]);
        }
        __syncthreads();
    }

    // ---- RoPE epilogue (modes 2/3): rotate in registers, then tf32-round.
    if (mode >= 2) {
        const float qs = (mode == 2) ? 0.125f : 1.0f;
        #pragma unroll
        for (int mi = 0; mi < 4; mi++) {
            #pragma unroll
            for (int rh = 0; rh < 2; rh++) {
                const int row = crow0 + wm * 64 + mi * 16 + gid + rh * 8;
                const int s   = row & (SEQ - 1);
                const float* cr = cosp + s * HDIM;
                const float* sr = sinp + s * HDIM;
                #pragma unroll
                for (int ni = 0; ni < 4; ni++) {
                    const int d = ni * 8 + 2 * tig;      // < 32
                    const float2 c1 = *reinterpret_cast<const float2*>(cr + d);
                    const float2 s1 = *reinterpret_cast<const float2*>(sr + d);
                    const float2 c2 = *reinterpret_cast<const float2*>(cr + d + 32);
                    const float2 s2 = *reinterpret_cast<const float2*>(sr + d + 32);
                    const float v1a = acc[mi][ni    ][rh * 2 + 0];
                    const float v1b = acc[mi][ni    ][rh * 2 + 1];
                    const float v2a = acc[mi][ni + 4][rh * 2 + 0];
                    const float v2b = acc[mi][ni + 4][rh * 2 + 1];
                    acc[mi][ni    ][rh * 2 + 0] =
                        __uint_as_float(f2tf32((v1a * c1.x - v2a * s1.x) * qs));
                    acc[mi][ni    ][rh * 2 + 1] =
                        __uint_as_float(f2tf32((v1b * c1.y - v2b * s1.y) * qs));
                    acc[mi][ni + 4][rh * 2 + 0] =
                        __uint_as_float(f2tf32((v2a * c2.x + v1a * s2.x) * qs));
                    acc[mi][ni + 4][rh * 2 + 1] =
                        __uint_as_float(f2tf32((v2b * c2.y + v1b * s2.y) * qs));
                }
            }
        }
    }

    const bool rnd = (mode == 1);
    #pragma unroll
    for (int mi = 0; mi < 4; mi++) {
        const int row = crow0 + wm * 64 + mi * 16 + gid;
        #pragma unroll
        for (int ni = 0; ni < 8; ni++) {
            const int col = ccol0 + wn * 64 + ni * 8 + tig * 2;
            float v0 = acc[mi][ni][0], v1 = acc[mi][ni][1];
            float v2 = acc[mi][ni][2], v3 = acc[mi][ni][3];
            if (rnd) {
                v0 = __uint_as_float(f2tf32(v0));
                v1 = __uint_as_float(f2tf32(v1));
                v2 = __uint_as_float(f2tf32(v2));
                v3 = __uint_as_float(f2tf32(v3));
            }
            *reinterpret_cast<float2*>(&C[(size_t)row * DMODEL + col]) =
                make_float2(v0, v1);
            *reinterpret_cast<float2*>(&C[(size_t)(row + 8) * DMODEL + col]) =
                make_float2(v2, v3);
        }
    }
}

// Fused QKV (+RoPE): grid.x = 24 (3 weights x 8 col tiles), grid.y = 32
__global__ __launch_bounds__(128) void qkv_gemm_mma(
    const float* __restrict__ cosp, const float* __restrict__ sinp)
{
    const int g  = blockIdx.x >> 3;
    const int bx = blockIdx.x & 7;
    float* Cp; int mode;
    if      (g == 0) { Cp = g_q; mode = 2; }   // Q: rope + 1/8 + round
    else if (g == 1) { Cp = g_k; mode = 3; }   // K: rope + round
    else             { Cp = g_v; mode = 1; }   // V: round
    gemm_tile_w64(g_xc, g_wc + (size_t)g * DMODEL * DMODEL, Cp,
                  blockIdx.y * 128, bx * 128, mode, cosp, sinp);
}

__global__ __launch_bounds__(128) void out_gemm_mma(float* __restrict__ out)
{
    gemm_tile_w64(reinterpret_cast<const uint32_t*>(g_att),
                  g_wc + (size_t)3 * DMODEL * DMODEL, out,
                  blockIdx.y * 128, blockIdx.x * 128, 0, nullptr, nullptr);
}

// ===========================================================================
// Tensor-core causal flash attention (tf32 mma.sync), operands pre-rounded.
// Block: 256 threads (8 warps); two paired 128-row q-tiles (qt, 15-qt).
// K/V 64x64 tiles double-buffered via cp.async (bits already tf32).
// P round-trips through smem for the PV mma. Online softmax in fragments.
// ===========================================================================
#define AT_SK 68
#define AT_SV 72
#define AT_KFLOATS (64*AT_SK)               // 4352
#define AT_STAGE   (AT_KFLOATS + 64*AT_SV)  // 8960 floats per stage
#define AT_PS      (2*AT_STAGE)             // P/Q staging offset
#define AT_SMEM_BYTES ((AT_PS + 128*AT_SK) * 4)   // 106496

__global__ __launch_bounds__(256, 2) void attn_mma_kernel()
{
    extern __shared__ float sm[];
    const int tid = threadIdx.x, wid = tid >> 5, lane = tid & 31;
    const int gid = lane >> 2, tig = lane & 3;
    const int bh = blockIdx.y, b = bh >> 4, h = bh & 15;
    const float* Qg = g_q + (size_t)b * SEQ * DMODEL + h * HDIM;
    const float* Kg = g_k + (size_t)b * SEQ * DMODEL + h * HDIM;
    const float* Vg = g_v + (size_t)b * SEQ * DMODEL + h * HDIM;
    float*       Og = g_att + (size_t)b * SEQ * DMODEL + h * HDIM;

    for (int half = 0; half < 2; half++) {
        const int qt    = half ? (15 - (int)blockIdx.x) : (int)blockIdx.x;
        const int qrow0 = qt * 128;
        const int m0    = wid * 16;
        const int r0    = qrow0 + m0;

        __syncthreads();                       // Ps free from previous half
        for (int i = tid; i < 2048; i += 256) {
            const int row = i >> 4, c4 = (i & 15) * 4;
            *reinterpret_cast<float4*>(&sm[AT_PS + row * AT_SK + c4]) =
                *reinterpret_cast<const float4*>(
                    &Qg[(size_t)(qrow0 + row) * DMODEL + c4]);
        }
        __syncthreads();
        uint32_t qf[8][4];
        #pragma unroll
        for (int kb = 0; kb < 8; kb++) {
            const uint32_t* q0 = reinterpret_cast<const uint32_t*>(
                &sm[AT_PS + (m0 + gid) * AT_SK + kb * 8]);
            const uint32_t* q1 = q0 + 8 * AT_SK;
            qf[kb][0] = q0[tig];
            qf[kb][1] = q1[tig];
            qf[kb][2] = q0[tig + 4];
            qf[kb][3] = q1[tig + 4];
        }
        __syncthreads();

        float oacc[8][4];
        #pragma unroll
        for (int n = 0; n < 8; n++)
            #pragma unroll
            for (int r = 0; r < 4; r++) oacc[n][r] = 0.f;
        float mr0 = -CUDART_INF_F, mr1 = -CUDART_INF_F;
        float lr0 = 0.f, lr1 = 0.f;
        const int ktmax = 2 * qt + 1;

        auto load_kv = [&](int kt, int st) {
            const float* Kp = Kg + (size_t)(kt * 64) * DMODEL;
            const float* Vp = Vg + (size_t)(kt * 64) * DMODEL;
            const uint32_t kd = smem_u32(&sm[st * AT_STAGE]);
            const uint32_t vd = kd + AT_KFLOATS * 4;
            #pragma unroll
            for (int i = 0; i < 4; i++) {
                const int idx = i * 256 + tid;
                const int row = idx >> 4, c4 = (idx & 15) * 4;
                const size_t g = (size_t)row * DMODEL + c4;
                cp_async16(kd + (row * AT_SK + c4) * 4, Kp + g);
                cp_async16(vd + (row * AT_SV + c4) * 4, Vp + g);
            }
            CP_COMMIT();
        };

        load_kv(0, 0);
        for (int kt = 0; kt <= ktmax; kt++) {
            const int st = kt & 1;
            const int k0 = kt * 64;
            if (kt < ktmax) { load_kv(kt + 1, st ^ 1); CP_WAIT(1); }
            else            { CP_WAIT(0); }
            __syncthreads();

            if (k0 <= r0 + 15) {
                const uint32_t* Ksm =
                    reinterpret_cast<const uint32_t*>(&sm[st * AT_STAGE]);
                const uint32_t* Vsm = Ksm + AT_KFLOATS;

                float sacc[8][4];
                #pragma unroll
                for (int n = 0; n < 8; n++)
                    #pragma unroll
                    for (int r = 0; r < 4; r++) sacc[n][r] = 0.f;

                #pragma unroll
                for (int kb = 0; kb < 8; kb++) {
                    #pragma unroll
                    for (int n = 0; n < 8; n++) {
                        const uint32_t* kr =
                            &Ksm[(n * 8 + gid) * AT_SK + kb * 8 + tig];
                        uint32_t bfr[2] = { kr[0], kr[4] };
                        mma_tf32(sacc[n], qf[kb], bfr);
                    }
                }
                if (k0 + 63 > r0) {
                    const int row0 = r0 + gid, row1 = row0 + 8;
                    #pragma unroll
                    for (int n = 0; n < 8; n++) {
                        const int c = k0 + n * 8 + 2 * tig;
                        if (c     > row0) sacc[n][0] = -CUDART_INF_F;
                        if (c + 1 > row0) sacc[n][1] = -CUDART_INF_F;
                        if (c     > row1) sacc[n][2] = -CUDART_INF_F;
                        if (c + 1 > row1) sacc[n][3] = -CUDART_INF_F;
                    }
                }
                float cm0 = -CUDART_INF_F, cm1 = -CUDART_INF_F;
                #pragma unroll
                for (int n = 0; n < 8; n++) {
                    cm0 = fmaxf(cm0, fmaxf(sacc[n][0], sacc[n][1]));
                    cm1 = fmaxf(cm1, fmaxf(sacc[n][2], sacc[n][3]));
                }
                cm0 = fmaxf(cm0, __shfl_xor_sync(0xffffffffu, cm0, 1));
                cm0 = fmaxf(cm0, __shfl_xor_sync(0xffffffffu, cm0, 2));
                cm1 = fmaxf(cm1, __shfl_xor_sync(0xffffffffu, cm1, 1));
                cm1 = fmaxf(cm1, __shfl_xor_sync(0xffffffffu, cm1, 2));
                const float mn0 = fmaxf(mr0, cm0), mn1 = fmaxf(mr1, cm1);
                const float co0 = __expf(mr0 - mn0), co1 = __expf(mr1 - mn1);
                float ps0 = 0.f, ps1 = 0.f;
                uint32_t* Pw =
                    reinterpret_cast<uint32_t*>(&sm[AT_PS + m0 * AT_SK]);
                #pragma unroll
                for (int n = 0; n < 8; n++) {
                    const float p00 = __expf(sacc[n][0] - mn0);
                    const float p01 = __expf(sacc[n][1] - mn0);
                    const float p10 = __expf(sacc[n][2] - mn1);
                    const float p11 = __expf(sacc[n][3] - mn1);
                    ps0 += p00 + p01; ps1 += p10 + p11;
                    *reinterpret_cast<uint2*>(
                        &Pw[gid * AT_SK + n * 8 + 2 * tig]) =
                        make_uint2(f2tf32(p00), f2tf32(p01));
                    *reinterpret_cast<uint2*>(
                        &Pw[(gid + 8) * AT_SK + n * 8 + 2 * tig]) =
                        make_uint2(f2tf32(p10), f2tf32(p11));
                    oacc[n][0] *= co0; oacc[n][1] *= co0;
                    oacc[n][2] *= co1; oacc[n][3] *= co1;
                }
                ps0 += __shfl_xor_sync(0xffffffffu, ps0, 1);
                ps0 += __shfl_xor_sync(0xffffffffu, ps0, 2);
                ps1 += __shfl_xor_sync(0xffffffffu, ps1, 1);
                ps1 += __shfl_xor_sync(0xffffffffu, ps1, 2);
                lr0 = lr0 * co0 + ps0;  lr1 = lr1 * co1 + ps1;
                mr0 = mn0;  mr1 = mn1;
                __syncwarp();
                #pragma unroll
                for (int kb = 0; kb < 8; kb++) {
                    const uint32_t* pr = &Pw[gid * AT_SK + kb * 8 + tig];
                    uint32_t pf[4] = { pr[0], pr[8 * AT_SK],
                                       pr[4], pr[8 * AT_SK + 4] };
                    #pragma unroll
                    for (int n = 0; n < 8; n++) {
                        const uint32_t* vr =
                            &Vsm[(kb * 8 + tig) * AT_SV + n * 8 + gid];
                        uint32_t vb2[2] = { vr[0], vr[4 * AT_SV] };
                        mma_tf32(oacc[n], pf, vb2);
                    }
                }
            }
            __syncthreads();
        }

        // Write O tf32-rounded so out_gemm consumes bits directly.
        const float i0 = 1.f / lr0, i1 = 1.f / lr1;
        #pragma unroll
        for (int n = 0; n < 8; n++) {
            const int col = n * 8 + 2 * tig;
            *reinterpret_cast<float2*>(
                &Og[(size_t)(r0 + gid) * DMODEL + col]) =
                make_float2(__uint_as_float(f2tf32(oacc[n][0] * i0)),
                            __uint_as_float(f2tf32(oacc[n][1] * i0)));
            *reinterpret_cast<float2*>(
                &Og[(size_t)(r0 + gid + 8) * DMODEL + col]) =
                make_float2(__uint_as_float(f2tf32(oacc[n][2] * i1)),
                            __uint_as_float(f2tf32(oacc[n][3] * i1)));
        }
    }
}

// ---------------------------------------------------------------------------
extern "C" void kernel_launch(void* const* d_in, const int* in_sizes, int n_in,
                              void* d_out, int out_size)
{
    const float* x    = (const float*)d_in[0];
    const float* cosp = (const float*)d_in[1];
    const float* sinp = (const float*)d_in[2];
    const float* Wq   = (const float*)d_in[3];
    const float* Wk   = (const float*)d_in[4];
    const float* Wv   = (const float*)d_in[5];
    const float* Wo   = (const float*)d_in[6];
    float* out = (float*)d_out;

    cudaFuncSetAttribute(attn_mma_kernel,
        cudaFuncAttributeMaxDynamicSharedMemorySize, AT_SMEM_BYTES);

    convert_tf32_kernel<<<8192, 256>>>(x, Wq, Wk, Wv, Wo);
    qkv_gemm_mma<<<dim3(24, 32), 128>>>(cosp, sinp);
    attn_mma_kernel<<<dim3(8, 32), 256, AT_SMEM_BYTES>>>();
    out_gemm_mma<<<dim3(8, 32), 128>>>(out);
}

// round 12
// speedup vs baseline: 5.1312x; 1.0574x over previous
#include <cuda_runtime.h>
#include <math_constants.h>
#include <cstdint>

#define BATCH 2
#define SEQ 2048
#define DMODEL 1024
#define NHEADS 16
#define HDIM 64
#define ROWS (BATCH*SEQ)   // 4096

// Scratch (allocation-free rule: __device__ globals).
__device__ float    g_q[(size_t)ROWS * DMODEL];
__device__ float    g_k[(size_t)ROWS * DMODEL];
__device__ float    g_v[(size_t)ROWS * DMODEL];
__device__ float    g_att[(size_t)ROWS * DMODEL];
__device__ uint32_t g_xc[(size_t)ROWS * DMODEL];          // tf32 bits of x
__device__ uint32_t g_wc[(size_t)4 * DMODEL * DMODEL];    // tf32 bits of Wq,Wk,Wv,Wo

// ===========================================================================
// Helpers
// ===========================================================================
__device__ __forceinline__ uint32_t smem_u32(const void* p) {
    uint32_t a;
    asm("{ .reg .u64 t; cvta.to.shared.u64 t, %1; cvt.u32.u64 %0, t; }"
        : "=r"(a) : "l"(p));
    return a;
}
__device__ __forceinline__ void cp_async16(uint32_t dst, const void* src) {
    asm volatile("cp.async.cg.shared.global [%0], [%1], 16;"
                 :: "r"(dst), "l"(src));
}
#define CP_COMMIT() asm volatile("cp.async.commit_group;" ::: "memory")
#define CP_WAIT(n)  asm volatile("cp.async.wait_group %0;" :: "n"(n) : "memory")

__device__ __forceinline__ uint32_t f2tf32(float f) {
    uint32_t r;
    asm("cvt.rna.tf32.f32 %0, %1;" : "=r"(r) : "f"(f));
    return r;
}
__device__ __forceinline__ void mma_tf32(float c[4],
                                         const uint32_t a[4],
                                         const uint32_t b[2]) {
    asm volatile(
        "mma.sync.aligned.m16n8k8.row.col.f32.tf32.tf32.f32 "
        "{%0,%1,%2,%3}, {%4,%5,%6,%7}, {%8,%9}, {%0,%1,%2,%3};"
        : "+f"(c[0]), "+f"(c[1]), "+f"(c[2]), "+f"(c[3])
        : "r"(a[0]), "r"(a[1]), "r"(a[2]), "r"(a[3]), "r"(b[0]), "r"(b[1]));
}

// ===========================================================================
// Pre-pass: round x + all weights to tf32 bits once.
// 2M float4 slots: [0,1M) = x, then 256K per weight.
// ===========================================================================
__global__ __launch_bounds__(256) void convert_tf32_kernel(
    const float* __restrict__ x,  const float* __restrict__ wq,
    const float* __restrict__ wk, const float* __restrict__ wv,
    const float* __restrict__ wo)
{
    const int idx = blockIdx.x * 256 + threadIdx.x;   // float4 index
    const float* src;
    uint32_t*    dst;
    if (idx < (1 << 20)) {
        src = x + (size_t)idx * 4;
        dst = g_xc + (size_t)idx * 4;
    } else {
        const int j   = idx - (1 << 20);
        const int w   = j >> 18;                      // 256K float4 per W
        const int off = j & ((1 << 18) - 1);
        const float* ws = (w == 0) ? wq : (w == 1) ? wk : (w == 2) ? wv : wo;
        src = ws + (size_t)off * 4;
        dst = g_wc + (size_t)w * DMODEL * DMODEL + (size_t)off * 4;
    }
    const float4 v = *reinterpret_cast<const float4*>(src);
    *reinterpret_cast<uint4*>(dst) =
        make_uint4(f2tf32(v.x), f2tf32(v.y), f2tf32(v.z), f2tf32(v.w));
}

// ===========================================================================
// tf32 mma.sync SGEMM_NT on pre-rounded bits: C = A * Bw^T, 128x128 block
// tile, 4 warps (2x2), warp tile 64x64, 128 threads. BK=16 double-buffered
// in smem AND fragment double-buffered in registers (software pipeline:
// LDS for half-chunk i+1 in flight while MMAs for half-chunk i issue).
// Epilogue modes: 0 = plain store, 1 = tf32-round (V),
//                 2 = RoPE + 1/8 scale + round (Q), 3 = RoPE + round (K).
// ===========================================================================
constexpr int G_BK     = 16;
constexpr int G_NCHUNK = DMODEL / G_BK;    // 64
constexpr int G_SSTR   = 20;

__device__ __forceinline__ void gemm_tile_w64(
    const uint32_t* __restrict__ A, const uint32_t* __restrict__ Bw,
    float* __restrict__ C, int crow0, int ccol0, int mode,
    const float* __restrict__ cosp, const float* __restrict__ sinp)
{
    __shared__ uint32_t As[2][128][G_SSTR];
    __shared__ uint32_t Bs[2][128][G_SSTR];

    const int tid  = threadIdx.x;        // 0..127
    const int wid  = tid >> 5;
    const int lane = tid & 31;
    const int wm   = wid & 1;            // 64-row band
    const int wn   = wid >> 1;           // 64-col band
    const int gid  = lane >> 2;          // 0..7
    const int tig  = lane & 3;           // 0..3

    const uint32_t* gA = A  + (size_t)crow0 * DMODEL;
    const uint32_t* gB = Bw + (size_t)ccol0 * DMODEL;

    auto load_chunk = [&](int c) {
        const int st = c & 1;
        #pragma unroll
        for (int i = 0; i < 4; i++) {
            const int idx = i * 128 + tid;     // [0,512) float4 slots
            const int row = idx >> 2, c4 = idx & 3;
            const size_t g = (size_t)row * DMODEL + c * G_BK + c4 * 4;
            cp_async16(smem_u32(&As[st][row][c4 * 4]), gA + g);
            cp_async16(smem_u32(&Bs[st][row][c4 * 4]), gB + g);
        }
        CP_COMMIT();
    };

    float acc[4][8][4];
    #pragma unroll
    for (int mi = 0; mi < 4; mi++)
        #pragma unroll
        for (int ni = 0; ni < 8; ni++)
            #pragma unroll
            for (int r = 0; r < 4; r++) acc[mi][ni][r] = 0.f;

    uint32_t afA[4][4], bfA[8][2], afB[4][4], bfB[8][2];

    auto load_frags = [&](uint32_t af[4][4], uint32_t bf[8][2],
                          int st, int kb) {
        #pragma unroll
        for (int mi = 0; mi < 4; mi++) {
            const int r0 = wm * 64 + mi * 16 + gid;
            af[mi][0] = As[st][r0    ][kb + tig];
            af[mi][1] = As[st][r0 + 8][kb + tig];
            af[mi][2] = As[st][r0    ][kb + tig + 4];
            af[mi][3] = As[st][r0 + 8][kb + tig + 4];
        }
        #pragma unroll
        for (int ni = 0; ni < 8; ni++) {
            const int n0 = wn * 64 + ni * 8 + gid;
            bf[ni][0] = Bs[st][n0][kb + tig];
            bf[ni][1] = Bs[st][n0][kb + tig + 4];
        }
    };
    auto mma_all = [&](const uint32_t af[4][4], const uint32_t bf[8][2]) {
        #pragma unroll
        for (int mi = 0; mi < 4; mi++)
            #pragma unroll
            for (int ni = 0; ni < 8; ni++)
                mma_tf32(acc[mi][ni], af[mi], bf[ni]);
    };

    // Prologue: two smem stages in flight, first fragment set resident.
    load_chunk(0);
    load_chunk(1);
    CP_WAIT(1);          // chunk 0 landed
    __syncthreads();
    load_frags(afA, bfA, 0, 0);

    for (int c = 0; c < G_NCHUNK; c++) {
        const int st = c & 1;
        load_frags(afB, bfB, st, 8);          // (c, ks=1) — LDS in flight...
        mma_all(afA, bfA);                    // ...behind these MMAs (c, ks=0)
        __syncthreads();                      // all reads of stage st done
        if (c + 2 < G_NCHUNK) load_chunk(c + 2);   // refill stage st
        else                  CP_COMMIT();         // keep group accounting uniform
        CP_WAIT(1);                           // chunk c+1 landed in st^1
        __syncthreads();
        if (c + 1 < G_NCHUNK)
            load_frags(afA, bfA, st ^ 1, 0);  // (c+1, ks=0) in flight...
        mma_all(afB, bfB);                    // ...behind these MMAs (c, ks=1)
    }

    // ---- RoPE epilogue (modes 2/3): rotate in registers, then tf32-round.
    if (mode >= 2) {
        const float qs = (mode == 2) ? 0.125f : 1.0f;
        #pragma unroll
        for (int mi = 0; mi < 4; mi++) {
            #pragma unroll
            for (int rh = 0; rh < 2; rh++) {
                const int row = crow0 + wm * 64 + mi * 16 + gid + rh * 8;
                const int s   = row & (SEQ - 1);
                const float* cr = cosp + s * HDIM;
                const float* sr = sinp + s * HDIM;
                #pragma unroll
                for (int ni = 0; ni < 4; ni++) {
                    const int d = ni * 8 + 2 * tig;      // < 32
                    const float2 c1 = *reinterpret_cast<const float2*>(cr + d);
                    const float2 s1 = *reinterpret_cast<const float2*>(sr + d);
                    const float2 c2 = *reinterpret_cast<const float2*>(cr + d + 32);
                    const float2 s2 = *reinterpret_cast<const float2*>(sr + d + 32);
                    const float v1a = acc[mi][ni    ][rh * 2 + 0];
                    const float v1b = acc[mi][ni    ][rh * 2 + 1];
                    const float v2a = acc[mi][ni + 4][rh * 2 + 0];
                    const float v2b = acc[mi][ni + 4][rh * 2 + 1];
                    acc[mi][ni    ][rh * 2 + 0] =
                        __uint_as_float(f2tf32((v1a * c1.x - v2a * s1.x) * qs));
                    acc[mi][ni    ][rh * 2 + 1] =
                        __uint_as_float(f2tf32((v1b * c1.y - v2b * s1.y) * qs));
                    acc[mi][ni + 4][rh * 2 + 0] =
                        __uint_as_float(f2tf32((v2a * c2.x + v1a * s2.x) * qs));
                    acc[mi][ni + 4][rh * 2 + 1] =
                        __uint_as_float(f2tf32((v2b * c2.y + v1b * s2.y) * qs));
                }
            }
        }
    }

    const bool rnd = (mode == 1);
    #pragma unroll
    for (int mi = 0; mi < 4; mi++) {
        const int row = crow0 + wm * 64 + mi * 16 + gid;
        #pragma unroll
        for (int ni = 0; ni < 8; ni++) {
            const int col = ccol0 + wn * 64 + ni * 8 + tig * 2;
            float v0 = acc[mi][ni][0], v1 = acc[mi][ni][1];
            float v2 = acc[mi][ni][2], v3 = acc[mi][ni][3];
            if (rnd) {
                v0 = __uint_as_float(f2tf32(v0));
                v1 = __uint_as_float(f2tf32(v1));
                v2 = __uint_as_float(f2tf32(v2));
                v3 = __uint_as_float(f2tf32(v3));
            }
            *reinterpret_cast<float2*>(&C[(size_t)row * DMODEL + col]) =
                make_float2(v0, v1);
            *reinterpret_cast<float2*>(&C[(size_t)(row + 8) * DMODEL + col]) =
                make_float2(v2, v3);
        }
    }
}

// Fused QKV (+RoPE): grid.x = 24 (3 weights x 8 col tiles), grid.y = 32
__global__ __launch_bounds__(128) void qkv_gemm_mma(
    const float* __restrict__ cosp, const float* __restrict__ sinp)
{
    const int g  = blockIdx.x >> 3;
    const int bx = blockIdx.x & 7;
    float* Cp; int mode;
    if      (g == 0) { Cp = g_q; mode = 2; }   // Q: rope + 1/8 + round
    else if (g == 1) { Cp = g_k; mode = 3; }   // K: rope + round
    else             { Cp = g_v; mode = 1; }   // V: round
    gemm_tile_w64(g_xc, g_wc + (size_t)g * DMODEL * DMODEL, Cp,
                  blockIdx.y * 128, bx * 128, mode, cosp, sinp);
}

__global__ __launch_bounds__(128) void out_gemm_mma(float* __restrict__ out)
{
    gemm_tile_w64(reinterpret_cast<const uint32_t*>(g_att),
                  g_wc + (size_t)3 * DMODEL * DMODEL, out,
                  blockIdx.y * 128, blockIdx.x * 128, 0, nullptr, nullptr);
}

// ===========================================================================
// Tensor-core causal flash attention (tf32 mma.sync), operands pre-rounded.
// Block: 256 threads (8 warps); two paired 128-row q-tiles (qt, 15-qt).
// K/V 64x64 tiles double-buffered via cp.async (bits already tf32).
// P round-trips through smem for the PV mma. Online softmax in fragments.
// ===========================================================================
#define AT_SK 68
#define AT_SV 72
#define AT_KFLOATS (64*AT_SK)               // 4352
#define AT_STAGE   (AT_KFLOATS + 64*AT_SV)  // 8960 floats per stage
#define AT_PS      (2*AT_STAGE)             // P/Q staging offset
#define AT_SMEM_BYTES ((AT_PS + 128*AT_SK) * 4)   // 106496

__global__ __launch_bounds__(256, 2) void attn_mma_kernel()
{
    extern __shared__ float sm[];
    const int tid = threadIdx.x, wid = tid >> 5, lane = tid & 31;
    const int gid = lane >> 2, tig = lane & 3;
    const int bh = blockIdx.y, b = bh >> 4, h = bh & 15;
    const float* Qg = g_q + (size_t)b * SEQ * DMODEL + h * HDIM;
    const float* Kg = g_k + (size_t)b * SEQ * DMODEL + h * HDIM;
    const float* Vg = g_v + (size_t)b * SEQ * DMODEL + h * HDIM;
    float*       Og = g_att + (size_t)b * SEQ * DMODEL + h * HDIM;

    for (int half = 0; half < 2; half++) {
        const int qt    = half ? (15 - (int)blockIdx.x) : (int)blockIdx.x;
        const int qrow0 = qt * 128;
        const int m0    = wid * 16;
        const int r0    = qrow0 + m0;

        __syncthreads();                       // Ps free from previous half
        for (int i = tid; i < 2048; i += 256) {
            const int row = i >> 4, c4 = (i & 15) * 4;
            *reinterpret_cast<float4*>(&sm[AT_PS + row * AT_SK + c4]) =
                *reinterpret_cast<const float4*>(
                    &Qg[(size_t)(qrow0 + row) * DMODEL + c4]);
        }
        __syncthreads();
        uint32_t qf[8][4];
        #pragma unroll
        for (int kb = 0; kb < 8; kb++) {
            const uint32_t* q0 = reinterpret_cast<const uint32_t*>(
                &sm[AT_PS + (m0 + gid) * AT_SK + kb * 8]);
            const uint32_t* q1 = q0 + 8 * AT_SK;
            qf[kb][0] = q0[tig];
            qf[kb][1] = q1[tig];
            qf[kb][2] = q0[tig + 4];
            qf[kb][3] = q1[tig + 4];
        }
        __syncthreads();

        float oacc[8][4];
        #pragma unroll
        for (int n = 0; n < 8; n++)
            #pragma unroll
            for (int r = 0; r < 4; r++) oacc[n][r] = 0.f;
        float mr0 = -CUDART_INF_F, mr1 = -CUDART_INF_F;
        float lr0 = 0.f, lr1 = 0.f;
        const int ktmax = 2 * qt + 1;

        auto load_kv = [&](int kt, int st) {
            const float* Kp = Kg + (size_t)(kt * 64) * DMODEL;
            const float* Vp = Vg + (size_t)(kt * 64) * DMODEL;
            const uint32_t kd = smem_u32(&sm[st * AT_STAGE]);
            const uint32_t vd = kd + AT_KFLOATS * 4;
            #pragma unroll
            for (int i = 0; i < 4; i++) {
                const int idx = i * 256 + tid;
                const int row = idx >> 4, c4 = (idx & 15) * 4;
                const size_t g = (size_t)row * DMODEL + c4;
                cp_async16(kd + (row * AT_SK + c4) * 4, Kp + g);
                cp_async16(vd + (row * AT_SV + c4) * 4, Vp + g);
            }
            CP_COMMIT();
        };

        load_kv(0, 0);
        for (int kt = 0; kt <= ktmax; kt++) {
            const int st = kt & 1;
            const int k0 = kt * 64;
            if (kt < ktmax) { load_kv(kt + 1, st ^ 1); CP_WAIT(1); }
            else            { CP_WAIT(0); }
            __syncthreads();

            if (k0 <= r0 + 15) {
                const uint32_t* Ksm =
                    reinterpret_cast<const uint32_t*>(&sm[st * AT_STAGE]);
                const uint32_t* Vsm = Ksm + AT_KFLOATS;

                float sacc[8][4];
                #pragma unroll
                for (int n = 0; n < 8; n++)
                    #pragma unroll
                    for (int r = 0; r < 4; r++) sacc[n][r] = 0.f;

                #pragma unroll
                for (int kb = 0; kb < 8; kb++) {
                    #pragma unroll
                    for (int n = 0; n < 8; n++) {
                        const uint32_t* kr =
                            &Ksm[(n * 8 + gid) * AT_SK + kb * 8 + tig];
                        uint32_t bfr[2] = { kr[0], kr[4] };
                        mma_tf32(sacc[n], qf[kb], bfr);
                    }
                }
                if (k0 + 63 > r0) {
                    const int row0 = r0 + gid, row1 = row0 + 8;
                    #pragma unroll
                    for (int n = 0; n < 8; n++) {
                        const int c = k0 + n * 8 + 2 * tig;
                        if (c     > row0) sacc[n][0] = -CUDART_INF_F;
                        if (c + 1 > row0) sacc[n][1] = -CUDART_INF_F;
                        if (c     > row1) sacc[n][2] = -CUDART_INF_F;
                        if (c + 1 > row1) sacc[n][3] = -CUDART_INF_F;
                    }
                }
                float cm0 = -CUDART_INF_F, cm1 = -CUDART_INF_F;
                #pragma unroll
                for (int n = 0; n < 8; n++) {
                    cm0 = fmaxf(cm0, fmaxf(sacc[n][0], sacc[n][1]));
                    cm1 = fmaxf(cm1, fmaxf(sacc[n][2], sacc[n][3]));
                }
                cm0 = fmaxf(cm0, __shfl_xor_sync(0xffffffffu, cm0, 1));
                cm0 = fmaxf(cm0, __shfl_xor_sync(0xffffffffu, cm0, 2));
                cm1 = fmaxf(cm1, __shfl_xor_sync(0xffffffffu, cm1, 1));
                cm1 = fmaxf(cm1, __shfl_xor_sync(0xffffffffu, cm1, 2));
                const float mn0 = fmaxf(mr0, cm0), mn1 = fmaxf(mr1, cm1);
                const float co0 = __expf(mr0 - mn0), co1 = __expf(mr1 - mn1);
                float ps0 = 0.f, ps1 = 0.f;
                uint32_t* Pw =
                    reinterpret_cast<uint32_t*>(&sm[AT_PS + m0 * AT_SK]);
                #pragma unroll
                for (int n = 0; n < 8; n++) {
                    const float p00 = __expf(sacc[n][0] - mn0);
                    const float p01 = __expf(sacc[n][1] - mn0);
                    const float p10 = __expf(sacc[n][2] - mn1);
                    const float p11 = __expf(sacc[n][3] - mn1);
                    ps0 += p00 + p01; ps1 += p10 + p11;
                    *reinterpret_cast<uint2*>(
                        &Pw[gid * AT_SK + n * 8 + 2 * tig]) =
                        make_uint2(f2tf32(p00), f2tf32(p01));
                    *reinterpret_cast<uint2*>(
                        &Pw[(gid + 8) * AT_SK + n * 8 + 2 * tig]) =
                        make_uint2(f2tf32(p10), f2tf32(p11));
                    oacc[n][0] *= co0; oacc[n][1] *= co0;
                    oacc[n][2] *= co1; oacc[n][3] *= co1;
                }
                ps0 += __shfl_xor_sync(0xffffffffu, ps0, 1);
                ps0 += __shfl_xor_sync(0xffffffffu, ps0, 2);
                ps1 += __shfl_xor_sync(0xffffffffu, ps1, 1);
                ps1 += __shfl_xor_sync(0xffffffffu, ps1, 2);
                lr0 = lr0 * co0 + ps0;  lr1 = lr1 * co1 + ps1;
                mr0 = mn0;  mr1 = mn1;
                __syncwarp();
                #pragma unroll
                for (int kb = 0; kb < 8; kb++) {
                    const uint32_t* pr = &Pw[gid * AT_SK + kb * 8 + tig];
                    uint32_t pf[4] = { pr[0], pr[8 * AT_SK],
                                       pr[4], pr[8 * AT_SK + 4] };
                    #pragma unroll
                    for (int n = 0; n < 8; n++) {
                        const uint32_t* vr =
                            &Vsm[(kb * 8 + tig) * AT_SV + n * 8 + gid];
                        uint32_t vb2[2] = { vr[0], vr[4 * AT_SV] };
                        mma_tf32(oacc[n], pf, vb2);
                    }
                }
            }
            __syncthreads();
        }

        // Write O tf32-rounded so out_gemm consumes bits directly.
        const float i0 = 1.f / lr0, i1 = 1.f / lr1;
        #pragma unroll
        for (int n = 0; n < 8; n++) {
            const int col = n * 8 + 2 * tig;
            *reinterpret_cast<float2*>(
                &Og[(size_t)(r0 + gid) * DMODEL + col]) =
                make_float2(__uint_as_float(f2tf32(oacc[n][0] * i0)),
                            __uint_as_float(f2tf32(oacc[n][1] * i0)));
            *reinterpret_cast<float2*>(
                &Og[(size_t)(r0 + gid + 8) * DMODEL + col]) =
                make_float2(__uint_as_float(f2tf32(oacc[n][2] * i1)),
                            __uint_as_float(f2tf32(oacc[n][3] * i1)));
        }
    }
}

// ---------------------------------------------------------------------------
extern "C" void kernel_launch(void* const* d_in, const int* in_sizes, int n_in,
                              void* d_out, int out_size)
{
    const float* x    = (const float*)d_in[0];
    const float* cosp = (const float*)d_in[1];
    const float* sinp = (const float*)d_in[2];
    const float* Wq   = (const float*)d_in[3];
    const float* Wk   = (const float*)d_in[4];
    const float* Wv   = (const float*)d_in[5];
    const float* Wo   = (const float*)d_in[6];
    float* out = (float*)d_out;

    cudaFuncSetAttribute(attn_mma_kernel,
        cudaFuncAttributeMaxDynamicSharedMemorySize, AT_SMEM_BYTES);

    convert_tf32_kernel<<<8192, 256>>>(x, Wq, Wk, Wv, Wo);
    qkv_gemm_mma<<<dim3(24, 32), 128>>>(cosp, sinp);
    attn_mma_kernel<<<dim3(8, 32), 256, AT_SMEM_BYTES>>>();
    out_gemm_mma<<<dim3(8, 32), 128>>>(out);
}

// round 14
// speedup vs baseline: 5.5978x; 1.0909x over previous
#include <cuda_runtime.h>
#include <math_constants.h>
#include <cstdint>

#define BATCH 2
#define SEQ 2048
#define DMODEL 1024
#define NHEADS 16
#define HDIM 64
#define ROWS (BATCH*SEQ)   // 4096

// Scratch (allocation-free rule: __device__ globals).
__device__ float    g_q[(size_t)ROWS * DMODEL];
__device__ float    g_k[(size_t)ROWS * DMODEL];
__device__ float    g_v[(size_t)ROWS * DMODEL];
__device__ float    g_att[(size_t)ROWS * DMODEL];
__device__ uint32_t g_xc[(size_t)ROWS * DMODEL];          // tf32 bits of x
__device__ uint32_t g_wc[(size_t)4 * DMODEL * DMODEL];    // tf32 bits of Wq,Wk,Wv,Wo

// ===========================================================================
// Helpers
// ===========================================================================
__device__ __forceinline__ uint32_t smem_u32(const void* p) {
    uint32_t a;
    asm("{ .reg .u64 t; cvta.to.shared.u64 t, %1; cvt.u32.u64 %0, t; }"
        : "=r"(a) : "l"(p));
    return a;
}
__device__ __forceinline__ void cp_async16(uint32_t dst, const void* src) {
    asm volatile("cp.async.cg.shared.global [%0], [%1], 16;"
                 :: "r"(dst), "l"(src));
}
#define CP_COMMIT() asm volatile("cp.async.commit_group;" ::: "memory")
#define CP_WAIT(n)  asm volatile("cp.async.wait_group %0;" :: "n"(n) : "memory")

__device__ __forceinline__ uint32_t f2tf32(float f) {
    uint32_t r;
    asm("cvt.rna.tf32.f32 %0, %1;" : "=r"(r) : "f"(f));
    return r;
}
__device__ __forceinline__ void mma_tf32(float c[4],
                                         const uint32_t a[4],
                                         const uint32_t b[2]) {
    asm volatile(
        "mma.sync.aligned.m16n8k8.row.col.f32.tf32.tf32.f32 "
        "{%0,%1,%2,%3}, {%4,%5,%6,%7}, {%8,%9}, {%0,%1,%2,%3};"
        : "+f"(c[0]), "+f"(c[1]), "+f"(c[2]), "+f"(c[3])
        : "r"(a[0]), "r"(a[1]), "r"(a[2]), "r"(a[3]), "r"(b[0]), "r"(b[1]));
}
// ldmatrix.x4: four 8x8 b16 tiles == the 16x8(x2) tf32 NT fragment pattern.
__device__ __forceinline__ void ldsm_x4(uint32_t& r0, uint32_t& r1,
                                        uint32_t& r2, uint32_t& r3,
                                        uint32_t addr) {
    asm volatile(
        "ldmatrix.sync.aligned.m8n8.x4.shared.b16 {%0,%1,%2,%3}, [%4];"
        : "=r"(r0), "=r"(r1), "=r"(r2), "=r"(r3) : "r"(addr));
}

// ===========================================================================
// Pre-pass: round x + all weights to tf32 bits once.
// ===========================================================================
__global__ __launch_bounds__(256) void convert_tf32_kernel(
    const float* __restrict__ x,  const float* __restrict__ wq,
    const float* __restrict__ wk, const float* __restrict__ wv,
    const float* __restrict__ wo)
{
    const int idx = blockIdx.x * 256 + threadIdx.x;   // float4 index
    const float* src;
    uint32_t*    dst;
    if (idx < (1 << 20)) {
        src = x + (size_t)idx * 4;
        dst = g_xc + (size_t)idx * 4;
    } else {
        const int j   = idx - (1 << 20);
        const int w   = j >> 18;                      // 256K float4 per W
        const int off = j & ((1 << 18) - 1);
        const float* ws = (w == 0) ? wq : (w == 1) ? wk : (w == 2) ? wv : wo;
        src = ws + (size_t)off * 4;
        dst = g_wc + (size_t)w * DMODEL * DMODEL + (size_t)off * 4;
    }
    const float4 v = *reinterpret_cast<const float4*>(src);
    *reinterpret_cast<uint4*>(dst) =
        make_uint4(f2tf32(v.x), f2tf32(v.y), f2tf32(v.z), f2tf32(v.w));
}

// ===========================================================================
// tf32 mma.sync SGEMM_NT on pre-rounded bits: C = A * Bw^T, 128x128 block
// tile, 4 warps (2x2), warp tile 64x64, 128 threads. BK=16 smem ping-pong +
// fragment double-buffer. Fragment loads via ldmatrix.x4 in UNIFORM code
// (1 LDSM = 16 LDS; 8-row phases cover all 32 banks with stride 20).
// Epilogue modes: 0 = plain store, 1 = tf32-round (V),
//                 2 = RoPE + 1/8 scale + round (Q), 3 = RoPE + round (K).
// ===========================================================================
constexpr int G_BK     = 16;
constexpr int G_NCHUNK = DMODEL / G_BK;    // 64
constexpr int G_SSTR   = 20;

__device__ __forceinline__ void gemm_tile_w64(
    const uint32_t* __restrict__ A, const uint32_t* __restrict__ Bw,
    float* __restrict__ C, int crow0, int ccol0, int mode,
    const float* __restrict__ cosp, const float* __restrict__ sinp)
{
    __shared__ __align__(16) uint32_t As[2][128][G_SSTR];
    __shared__ __align__(16) uint32_t Bs[2][128][G_SSTR];

    const int tid  = threadIdx.x;        // 0..127
    const int wid  = tid >> 5;
    const int lane = tid & 31;
    const int wm   = wid & 1;            // 64-row band
    const int wn   = wid >> 1;           // 64-col band
    const int gid  = lane >> 2;          // 0..7
    const int tig  = lane & 3;           // 0..3
    // ldmatrix per-lane addressing: quad q -> (row += (q&1)*8, col += (q>>1)*4)
    const int quad   = lane >> 3;
    const int i8     = lane & 7;
    const int rowoff = ((quad & 1) << 3) + i8;
    const int coloff = (quad >> 1) << 2;

    const uint32_t aBase0 = smem_u32(&As[0][wm * 64 + rowoff][coloff]);
    const uint32_t aBase1 = smem_u32(&As[1][wm * 64 + rowoff][coloff]);
    const uint32_t bBase0 = smem_u32(&Bs[0][wn * 64 + rowoff][coloff]);
    const uint32_t bBase1 = smem_u32(&Bs[1][wn * 64 + rowoff][coloff]);

    const uint32_t* gA = A  + (size_t)crow0 * DMODEL;
    const uint32_t* gB = Bw + (size_t)ccol0 * DMODEL;

    auto load_chunk = [&](int c) {
        const int st = c & 1;
        #pragma unroll
        for (int i = 0; i < 4; i++) {
            const int idx = i * 128 + tid;     // [0,512) float4 slots
            const int row = idx >> 2, c4 = idx & 3;
            const size_t g = (size_t)row * DMODEL + c * G_BK + c4 * 4;
            cp_async16(smem_u32(&As[st][row][c4 * 4]), gA + g);
            cp_async16(smem_u32(&Bs[st][row][c4 * 4]), gB + g);
        }
        CP_COMMIT();
    };

    float acc[4][8][4];
    #pragma unroll
    for (int mi = 0; mi < 4; mi++)
        #pragma unroll
        for (int ni = 0; ni < 8; ni++)
            #pragma unroll
            for (int r = 0; r < 4; r++) acc[mi][ni][r] = 0.f;

    uint32_t afA[4][4], bfA[8][2], afB[4][4], bfB[8][2];

    auto load_frags = [&](uint32_t af[4][4], uint32_t bf[8][2],
                          int st, int kb) {
        const uint32_t ab = (st ? aBase1 : aBase0) + kb * 4;
        const uint32_t bb = (st ? bBase1 : bBase0) + kb * 4;
        #pragma unroll
        for (int mi = 0; mi < 4; mi++)
            ldsm_x4(af[mi][0], af[mi][1], af[mi][2], af[mi][3],
                    ab + mi * (16 * G_SSTR * 4));
        #pragma unroll
        for (int p = 0; p < 4; p++) {
            uint32_t r0, r1, r2, r3;
            ldsm_x4(r0, r1, r2, r3, bb + p * (16 * G_SSTR * 4));
            bf[2 * p][0] = r0;  bf[2 * p + 1][0] = r1;
            bf[2 * p][1] = r2;  bf[2 * p + 1][1] = r3;
        }
    };
    auto mma_all = [&](const uint32_t af[4][4], const uint32_t bf[8][2]) {
        #pragma unroll
        for (int mi = 0; mi < 4; mi++)
            #pragma unroll
            for (int ni = 0; ni < 8; ni++)
                mma_tf32(acc[mi][ni], af[mi], bf[ni]);
    };

    // Prologue: two smem stages in flight, first fragment set resident.
    load_chunk(0);
    load_chunk(1);
    CP_WAIT(1);          // chunk 0 landed
    __syncthreads();
    load_frags(afA, bfA, 0, 0);

    for (int c = 0; c < G_NCHUNK; c++) {
        const int st = c & 1;
        load_frags(afB, bfB, st, 8);          // (c, ks=1) — LDSM in flight...
        mma_all(afA, bfA);                    // ...behind these MMAs (c, ks=0)
        __syncthreads();                      // all reads of stage st done
        if (c + 2 < G_NCHUNK) load_chunk(c + 2);   // refill stage st
        else                  CP_COMMIT();         // keep group accounting uniform
        CP_WAIT(1);                           // chunk c+1 landed in st^1
        __syncthreads();
        if (c + 1 < G_NCHUNK)
            load_frags(afA, bfA, st ^ 1, 0);  // (c+1, ks=0) in flight...
        mma_all(afB, bfB);                    // ...behind these MMAs (c, ks=1)
    }

    // ---- RoPE epilogue (modes 2/3): rotate in registers, then tf32-round.
    if (mode >= 2) {
        const float qs = (mode == 2) ? 0.125f : 1.0f;
        #pragma unroll
        for (int mi = 0; mi < 4; mi++) {
            #pragma unroll
            for (int rh = 0; rh < 2; rh++) {
                const int row = crow0 + wm * 64 + mi * 16 + gid + rh * 8;
                const int s   = row & (SEQ - 1);
                const float* cr = cosp + s * HDIM;
                const float* sr = sinp + s * HDIM;
                #pragma unroll
                for (int ni = 0; ni < 4; ni++) {
                    const int d = ni * 8 + 2 * tig;      // < 32
                    const float2 c1 = *reinterpret_cast<const float2*>(cr + d);
                    const float2 s1 = *reinterpret_cast<const float2*>(sr + d);
                    const float2 c2 = *reinterpret_cast<const float2*>(cr + d + 32);
                    const float2 s2 = *reinterpret_cast<const float2*>(sr + d + 32);
                    const float v1a = acc[mi][ni    ][rh * 2 + 0];
                    const float v1b = acc[mi][ni    ][rh * 2 + 1];
                    const float v2a = acc[mi][ni + 4][rh * 2 + 0];
                    const float v2b = acc[mi][ni + 4][rh * 2 + 1];
                    acc[mi][ni    ][rh * 2 + 0] =
                        __uint_as_float(f2tf32((v1a * c1.x - v2a * s1.x) * qs));
                    acc[mi][ni    ][rh * 2 + 1] =
                        __uint_as_float(f2tf32((v1b * c1.y - v2b * s1.y) * qs));
                    acc[mi][ni + 4][rh * 2 + 0] =
                        __uint_as_float(f2tf32((v2a * c2.x + v1a * s2.x) * qs));
                    acc[mi][ni + 4][rh * 2 + 1] =
                        __uint_as_float(f2tf32((v2b * c2.y + v1b * s2.y) * qs));
                }
            }
        }
    }

    const bool rnd = (mode == 1);
    #pragma unroll
    for (int mi = 0; mi < 4; mi++) {
        const int row = crow0 + wm * 64 + mi * 16 + gid;
        #pragma unroll
        for (int ni = 0; ni < 8; ni++) {
            const int col = ccol0 + wn * 64 + ni * 8 + tig * 2;
            float v0 = acc[mi][ni][0], v1 = acc[mi][ni][1];
            float v2 = acc[mi][ni][2], v3 = acc[mi][ni][3];
            if (rnd) {
                v0 = __uint_as_float(f2tf32(v0));
                v1 = __uint_as_float(f2tf32(v1));
                v2 = __uint_as_float(f2tf32(v2));
                v3 = __uint_as_float(f2tf32(v3));
            }
            *reinterpret_cast<float2*>(&C[(size_t)row * DMODEL + col]) =
                make_float2(v0, v1);
            *reinterpret_cast<float2*>(&C[(size_t)(row + 8) * DMODEL + col]) =
                make_float2(v2, v3);
        }
    }
}

// Fused QKV (+RoPE): grid.x = 24 (3 weights x 8 col tiles), grid.y = 32
__global__ __launch_bounds__(128) void qkv_gemm_mma(
    const float* __restrict__ cosp, const float* __restrict__ sinp)
{
    const int g  = blockIdx.x >> 3;
    const int bx = blockIdx.x & 7;
    float* Cp; int mode;
    if      (g == 0) { Cp = g_q; mode = 2; }   // Q: rope + 1/8 + round
    else if (g == 1) { Cp = g_k; mode = 3; }   // K: rope + round
    else             { Cp = g_v; mode = 1; }   // V: round
    gemm_tile_w64(g_xc, g_wc + (size_t)g * DMODEL * DMODEL, Cp,
                  blockIdx.y * 128, bx * 128, mode, cosp, sinp);
}

__global__ __launch_bounds__(128) void out_gemm_mma(float* __restrict__ out)
{
    gemm_tile_w64(reinterpret_cast<const uint32_t*>(g_att),
                  g_wc + (size_t)3 * DMODEL * DMODEL, out,
                  blockIdx.y * 128, blockIdx.x * 128, 0, nullptr, nullptr);
}

// ===========================================================================
// Tensor-core causal flash attention (tf32 mma.sync), operands pre-rounded.
// Block: 256 threads (8 warps); two paired 128-row q-tiles (qt, 15-qt).
// K/V 64x64 tiles double-buffered via cp.async (bits already tf32).
// P round-trips through smem for the PV mma. Online softmax in fragments.
// (R12 scalar-LDS version — known good; ldmatrix deliberately NOT used here.)
// ===========================================================================
#define AT_SK 68
#define AT_SV 72
#define AT_KFLOATS (64*AT_SK)               // 4352
#define AT_STAGE   (AT_KFLOATS + 64*AT_SV)  // 8960 floats per stage
#define AT_PS      (2*AT_STAGE)             // P/Q staging offset
#define AT_SMEM_BYTES ((AT_PS + 128*AT_SK) * 4)   // 106496

__global__ __launch_bounds__(256, 2) void attn_mma_kernel()
{
    extern __shared__ float sm[];
    const int tid = threadIdx.x, wid = tid >> 5, lane = tid & 31;
    const int gid = lane >> 2, tig = lane & 3;
    const int bh = blockIdx.y, b = bh >> 4, h = bh & 15;
    const float* Qg = g_q + (size_t)b * SEQ * DMODEL + h * HDIM;
    const float* Kg = g_k + (size_t)b * SEQ * DMODEL + h * HDIM;
    const float* Vg = g_v + (size_t)b * SEQ * DMODEL + h * HDIM;
    float*       Og = g_att + (size_t)b * SEQ * DMODEL + h * HDIM;

    for (int half = 0; half < 2; half++) {
        const int qt    = half ? (15 - (int)blockIdx.x) : (int)blockIdx.x;
        const int qrow0 = qt * 128;
        const int m0    = wid * 16;
        const int r0    = qrow0 + m0;

        __syncthreads();                       // Ps free from previous half
        for (int i = tid; i < 2048; i += 256) {
            const int row = i >> 4, c4 = (i & 15) * 4;
            *reinterpret_cast<float4*>(&sm[AT_PS + row * AT_SK + c4]) =
                *reinterpret_cast<const float4*>(
                    &Qg[(size_t)(qrow0 + row) * DMODEL + c4]);
        }
        __syncthreads();
        uint32_t qf[8][4];
        #pragma unroll
        for (int kb = 0; kb < 8; kb++) {
            const uint32_t* q0 = reinterpret_cast<const uint32_t*>(
                &sm[AT_PS + (m0 + gid) * AT_SK + kb * 8]);
            const uint32_t* q1 = q0 + 8 * AT_SK;
            qf[kb][0] = q0[tig];
            qf[kb][1] = q1[tig];
            qf[kb][2] = q0[tig + 4];
            qf[kb][3] = q1[tig + 4];
        }
        __syncthreads();

        float oacc[8][4];
        #pragma unroll
        for (int n = 0; n < 8; n++)
            #pragma unroll
            for (int r = 0; r < 4; r++) oacc[n][r] = 0.f;
        float mr0 = -CUDART_INF_F, mr1 = -CUDART_INF_F;
        float lr0 = 0.f, lr1 = 0.f;
        const int ktmax = 2 * qt + 1;

        auto load_kv = [&](int kt, int st) {
            const float* Kp = Kg + (size_t)(kt * 64) * DMODEL;
            const float* Vp = Vg + (size_t)(kt * 64) * DMODEL;
            const uint32_t kd = smem_u32(&sm[st * AT_STAGE]);
            const uint32_t vd = kd + AT_KFLOATS * 4;
            #pragma unroll
            for (int i = 0; i < 4; i++) {
                const int idx = i * 256 + tid;
                const int row = idx >> 4, c4 = (idx & 15) * 4;
                const size_t g = (size_t)row * DMODEL + c4;
                cp_async16(kd + (row * AT_SK + c4) * 4, Kp + g);
                cp_async16(vd + (row * AT_SV + c4) * 4, Vp + g);
            }
            CP_COMMIT();
        };

        load_kv(0, 0);
        for (int kt = 0; kt <= ktmax; kt++) {
            const int st = kt & 1;
            const int k0 = kt * 64;
            if (kt < ktmax) { load_kv(kt + 1, st ^ 1); CP_WAIT(1); }
            else            { CP_WAIT(0); }
            __syncthreads();

            if (k0 <= r0 + 15) {
                const uint32_t* Ksm =
                    reinterpret_cast<const uint32_t*>(&sm[st * AT_STAGE]);
                const uint32_t* Vsm = Ksm + AT_KFLOATS;

                float sacc[8][4];
                #pragma unroll
                for (int n = 0; n < 8; n++)
                    #pragma unroll
                    for (int r = 0; r < 4; r++) sacc[n][r] = 0.f;

                #pragma unroll
                for (int kb = 0; kb < 8; kb++) {
                    #pragma unroll
                    for (int n = 0; n < 8; n++) {
                        const uint32_t* kr =
                            &Ksm[(n * 8 + gid) * AT_SK + kb * 8 + tig];
                        uint32_t bfr[2] = { kr[0], kr[4] };
                        mma_tf32(sacc[n], qf[kb], bfr);
                    }
                }
                if (k0 + 63 > r0) {
                    const int row0 = r0 + gid, row1 = row0 + 8;
                    #pragma unroll
                    for (int n = 0; n < 8; n++) {
                        const int c = k0 + n * 8 + 2 * tig;
                        if (c     > row0) sacc[n][0] = -CUDART_INF_F;
                        if (c + 1 > row0) sacc[n][1] = -CUDART_INF_F;
                        if (c     > row1) sacc[n][2] = -CUDART_INF_F;
                        if (c + 1 > row1) sacc[n][3] = -CUDART_INF_F;
                    }
                }
                float cm0 = -CUDART_INF_F, cm1 = -CUDART_INF_F;
                #pragma unroll
                for (int n = 0; n < 8; n++) {
                    cm0 = fmaxf(cm0, fmaxf(sacc[n][0], sacc[n][1]));
                    cm1 = fmaxf(cm1, fmaxf(sacc[n][2], sacc[n][3]));
                }
                cm0 = fmaxf(cm0, __shfl_xor_sync(0xffffffffu, cm0, 1));
                cm0 = fmaxf(cm0, __shfl_xor_sync(0xffffffffu, cm0, 2));
                cm1 = fmaxf(cm1, __shfl_xor_sync(0xffffffffu, cm1, 1));
                cm1 = fmaxf(cm1, __shfl_xor_sync(0xffffffffu, cm1, 2));
                const float mn0 = fmaxf(mr0, cm0), mn1 = fmaxf(mr1, cm1);
                const float co0 = __expf(mr0 - mn0), co1 = __expf(mr1 - mn1);
                float ps0 = 0.f, ps1 = 0.f;
                uint32_t* Pw =
                    reinterpret_cast<uint32_t*>(&sm[AT_PS + m0 * AT_SK]);
                #pragma unroll
                for (int n = 0; n < 8; n++) {
                    const float p00 = __expf(sacc[n][0] - mn0);
                    const float p01 = __expf(sacc[n][1] - mn0);
                    const float p10 = __expf(sacc[n][2] - mn1);
                    const float p11 = __expf(sacc[n][3] - mn1);
                    ps0 += p00 + p01; ps1 += p10 + p11;
                    *reinterpret_cast<uint2*>(
                        &Pw[gid * AT_SK + n * 8 + 2 * tig]) =
                        make_uint2(f2tf32(p00), f2tf32(p01));
                    *reinterpret_cast<uint2*>(
                        &Pw[(gid + 8) * AT_SK + n * 8 + 2 * tig]) =
                        make_uint2(f2tf32(p10), f2tf32(p11));
                    oacc[n][0] *= co0; oacc[n][1] *= co0;
                    oacc[n][2] *= co1; oacc[n][3] *= co1;
                }
                ps0 += __shfl_xor_sync(0xffffffffu, ps0, 1);
                ps0 += __shfl_xor_sync(0xffffffffu, ps0, 2);
                ps1 += __shfl_xor_sync(0xffffffffu, ps1, 1);
                ps1 += __shfl_xor_sync(0xffffffffu, ps1, 2);
                lr0 = lr0 * co0 + ps0;  lr1 = lr1 * co1 + ps1;
                mr0 = mn0;  mr1 = mn1;
                __syncwarp();
                #pragma unroll
                for (int kb = 0; kb < 8; kb++) {
                    const uint32_t* pr = &Pw[gid * AT_SK + kb * 8 + tig];
                    uint32_t pf[4] = { pr[0], pr[8 * AT_SK],
                                       pr[4], pr[8 * AT_SK + 4] };
                    #pragma unroll
                    for (int n = 0; n < 8; n++) {
                        const uint32_t* vr =
                            &Vsm[(kb * 8 + tig) * AT_SV + n * 8 + gid];
                        uint32_t vb2[2] = { vr[0], vr[4 * AT_SV] };
                        mma_tf32(oacc[n], pf, vb2);
                    }
                }
            }
            __syncthreads();
        }

        // Write O tf32-rounded so out_gemm consumes bits directly.
        const float i0 = 1.f / lr0, i1 = 1.f / lr1;
        #pragma unroll
        for (int n = 0; n < 8; n++) {
            const int col = n * 8 + 2 * tig;
            *reinterpret_cast<float2*>(
                &Og[(size_t)(r0 + gid) * DMODEL + col]) =
                make_float2(__uint_as_float(f2tf32(oacc[n][0] * i0)),
                            __uint_as_float(f2tf32(oacc[n][1] * i0)));
            *reinterpret_cast<float2*>(
                &Og[(size_t)(r0 + gid + 8) * DMODEL + col]) =
                make_float2(__uint_as_float(f2tf32(oacc[n][2] * i1)),
                            __uint_as_float(f2tf32(oacc[n][3] * i1)));
        }
    }
}

// ---------------------------------------------------------------------------
extern "C" void kernel_launch(void* const* d_in, const int* in_sizes, int n_in,
                              void* d_out, int out_size)
{
    const float* x    = (const float*)d_in[0];
    const float* cosp = (const float*)d_in[1];
    const float* sinp = (const float*)d_in[2];
    const float* Wq   = (const float*)d_in[3];
    const float* Wk   = (const float*)d_in[4];
    const float* Wv   = (const float*)d_in[5];
    const float* Wo   = (const float*)d_in[6];
    float* out = (float*)d_out;

    cudaFuncSetAttribute(attn_mma_kernel,
        cudaFuncAttributeMaxDynamicSharedMemorySize, AT_SMEM_BYTES);

    convert_tf32_kernel<<<8192, 256>>>(x, Wq, Wk, Wv, Wo);
    qkv_gemm_mma<<<dim3(24, 32), 128>>>(cosp, sinp);
    attn_mma_kernel<<<dim3(8, 32), 256, AT_SMEM_BYTES>>>();
    out_gemm_mma<<<dim3(8, 32), 128>>>(out);
}